// round 11
// baseline (speedup 1.0000x reference)
#include <cuda_runtime.h>
#include <math.h>
#include <stdint.h>

#define BATCH 4
#define SEQ   1024
#define DM    1024
#define NH    16
#define DH    64

// Scratch (device globals — no allocation allowed)
__device__ float g_q[(size_t)BATCH*NH*SEQ*DH];   // [b*NH+h][s][d]
__device__ float g_k[(size_t)BATCH*SEQ*DH];      // [b*S+s][d]
__device__ float g_v[(size_t)BATCH*SEQ*DH];
__device__ float g_ctx[(size_t)BATCH*SEQ*DM];    // [b*S+s][h*DH+d]

// ---------------------------------------------------------------------------
// TF32 helpers
// ---------------------------------------------------------------------------
__device__ __forceinline__ float f2tf(float x) {
    uint32_t u;
    asm("cvt.rna.tf32.f32 %0, %1;" : "=r"(u) : "f"(x));
    return __uint_as_float(u);
}

__device__ __forceinline__ void mma_tf32(float* c, const uint32_t* a, const uint32_t* b) {
    asm volatile(
        "mma.sync.aligned.m16n8k8.row.col.f32.tf32.tf32.f32 "
        "{%0,%1,%2,%3}, {%4,%5,%6,%7}, {%8,%9}, {%0,%1,%2,%3};\n"
        : "+f"(c[0]), "+f"(c[1]), "+f"(c[2]), "+f"(c[3])
        : "r"(a[0]), "r"(a[1]), "r"(a[2]), "r"(a[3]), "r"(b[0]), "r"(b[1]));
}

__device__ __forceinline__ void l2_prefetch(const void* p) {
    asm volatile("prefetch.global.L2 [%0];" :: "l"(p));
}

// ---------------------------------------------------------------------------
// TF32 GEMM, double-buffered smem (1 barrier per k-iter). (R8, unchanged)
// MODE 2: out = A @ Wo^T + bias
// MODE 4: fused projections: x<8 -> q permuted; x==8 -> k,v.
// ---------------------------------------------------------------------------
#define GP 20

template<int MODE>
__global__ __launch_bounds__(256, 2)
void gemm_tf32(const float* __restrict__ A, const float* __restrict__ B,
               const float* __restrict__ Bk, const float* __restrict__ Bv,
               const float* __restrict__ bias,
               float* __restrict__ C, float* __restrict__ Ck, float* __restrict__ Cv,
               int M, int N, int K)
{
    __shared__ float sA[2][128 * GP];
    __shared__ float sB[2][128 * GP];

    const int tid  = threadIdx.x;
    const int lane = tid & 31;
    const int w    = tid >> 5;
    const int wr   = w >> 1;
    const int wc   = w & 1;
    const int g    = lane >> 2;
    const int t    = lane & 3;
    const int m0   = blockIdx.y * 128;
    const bool kv  = (MODE == 4) && (blockIdx.x == 8);
    const int n0   = kv ? 0 : blockIdx.x * 128;

    const int ldr = tid >> 2;
    const int ldc = (tid & 3) * 4;

    float acc[2][8][4];
    #pragma unroll
    for (int mt = 0; mt < 2; mt++)
        #pragma unroll
        for (int nt = 0; nt < 8; nt++)
            #pragma unroll
            for (int q = 0; q < 4; q++) acc[mt][nt][q] = 0.f;

    float4 ar[2], br[2];

    #pragma unroll
    for (int h = 0; h < 2; h++) {
        const int row = ldr + h * 64;
        ar[h] = *(const float4*)&A[(size_t)(m0 + row) * K + ldc];
        if (MODE == 4 && kv) {
            const float* Bs = (row >= 64) ? Bv : Bk;
            br[h] = *(const float4*)&Bs[(size_t)(row & 63) * K + ldc];
        } else {
            br[h] = *(const float4*)&B[(size_t)(n0 + row) * K + ldc];
        }
    }
    {
        #pragma unroll
        for (int h = 0; h < 2; h++) {
            const int row = ldr + h * 64;
            float* da = &sA[0][row * GP + ldc];
            da[0] = f2tf(ar[h].x); da[1] = f2tf(ar[h].y);
            da[2] = f2tf(ar[h].z); da[3] = f2tf(ar[h].w);
            float* db = &sB[0][row * GP + ldc];
            db[0] = f2tf(br[h].x); db[1] = f2tf(br[h].y);
            db[2] = f2tf(br[h].z); db[3] = f2tf(br[h].w);
        }
        #pragma unroll
        for (int h = 0; h < 2; h++) {
            const int row = ldr + h * 64;
            ar[h] = *(const float4*)&A[(size_t)(m0 + row) * K + 16 + ldc];
            if (MODE == 4 && kv) {
                const float* Bs = (row >= 64) ? Bv : Bk;
                br[h] = *(const float4*)&Bs[(size_t)(row & 63) * K + 16 + ldc];
            } else {
                br[h] = *(const float4*)&B[(size_t)(n0 + row) * K + 16 + ldc];
            }
        }
    }
    __syncthreads();

    const int nIt = K >> 4;
    for (int it = 0; it < nIt; it++) {
        const int buf = it & 1;
        const float* cA = sA[buf];
        const float* cB = sB[buf];

        #pragma unroll
        for (int ks = 0; ks < 2; ks++) {
            const int k = ks * 8;
            uint32_t af[2][4], bf[8][2];
            #pragma unroll
            for (int mt = 0; mt < 2; mt++) {
                const int mr = wr * 32 + mt * 16;
                af[mt][0] = __float_as_uint(cA[(mr + g) * GP + k + t]);
                af[mt][1] = __float_as_uint(cA[(mr + g + 8) * GP + k + t]);
                af[mt][2] = __float_as_uint(cA[(mr + g) * GP + k + t + 4]);
                af[mt][3] = __float_as_uint(cA[(mr + g + 8) * GP + k + t + 4]);
            }
            #pragma unroll
            for (int nt = 0; nt < 8; nt++) {
                const int nn = wc * 64 + nt * 8 + g;
                bf[nt][0] = __float_as_uint(cB[nn * GP + k + t]);
                bf[nt][1] = __float_as_uint(cB[nn * GP + k + t + 4]);
            }
            #pragma unroll
            for (int mt = 0; mt < 2; mt++)
                #pragma unroll
                for (int nt = 0; nt < 8; nt++)
                    mma_tf32(acc[mt][nt], af[mt], bf[nt]);
        }

        if (it + 1 < nIt) {
            float* dA = sA[buf ^ 1];
            float* dB = sB[buf ^ 1];
            #pragma unroll
            for (int h = 0; h < 2; h++) {
                const int row = ldr + h * 64;
                float* da = &dA[row * GP + ldc];
                da[0] = f2tf(ar[h].x); da[1] = f2tf(ar[h].y);
                da[2] = f2tf(ar[h].z); da[3] = f2tf(ar[h].w);
                float* db = &dB[row * GP + ldc];
                db[0] = f2tf(br[h].x); db[1] = f2tf(br[h].y);
                db[2] = f2tf(br[h].z); db[3] = f2tf(br[h].w);
            }
            if (it + 2 < nIt) {
                const int k0 = (it + 2) * 16;
                #pragma unroll
                for (int h = 0; h < 2; h++) {
                    const int row = ldr + h * 64;
                    ar[h] = *(const float4*)&A[(size_t)(m0 + row) * K + k0 + ldc];
                    if (MODE == 4 && kv) {
                        const float* Bs = (row >= 64) ? Bv : Bk;
                        br[h] = *(const float4*)&Bs[(size_t)(row & 63) * K + k0 + ldc];
                    } else {
                        br[h] = *(const float4*)&B[(size_t)(n0 + row) * K + k0 + ldc];
                    }
                }
            }
        }
        __syncthreads();
    }

    #pragma unroll
    for (int mt = 0; mt < 2; mt++) {
        #pragma unroll
        for (int rr = 0; rr < 2; rr++) {
            const int m = m0 + wr * 32 + mt * 16 + g + rr * 8;
            #pragma unroll
            for (int nt = 0; nt < 8; nt++) {
                const int n = n0 + wc * 64 + nt * 8 + 2 * t;
                const float v0 = acc[mt][nt][rr * 2 + 0];
                const float v1 = acc[mt][nt][rr * 2 + 1];
                if (MODE == 2) {
                    *(float2*)&C[(size_t)m * N + n] =
                        make_float2(v0 + bias[n], v1 + bias[n + 1]);
                } else if (MODE == 4 && !kv) {
                    const int b = m >> 10, s = m & 1023;
                    const int h = n >> 6, d = n & 63;
                    *(float2*)&C[(((size_t)(b * NH + h)) * SEQ + s) * DH + d] =
                        make_float2(v0, v1);
                } else {
                    float* dst = wc ? Cv : Ck;
                    const int nn = nt * 8 + 2 * t;
                    *(float2*)&dst[(size_t)m * 64 + nn] = make_float2(v0, v1);
                }
            }
        }
    }
}

// ---------------------------------------------------------------------------
// Fused attention v3: scores B-fragments (K + rel) loaded DIRECTLY from
// gmem (sector-perfect pattern, immediate offsets), no KR smem build.
// V gets its own smem region, loaded at tile-top overlapping scores MMA.
// 3 barriers/tile. One CTA per query i; 8 warps = (batch, half); 2 CTAs/SM.
// ---------------------------------------------------------------------------
#define AP 68   // pitch for sQ / sP
#define VP 72   // pitch for V rows (72 % 32 == 8 -> AV B-frag conflict-free)

#define SM_Q   (64 * AP)
#define SM_V   (4 * 64 * VP)
#define SM_P   (64 * AP)
#define SM_ATTN_FLOATS (SM_Q + SM_V + SM_P + 2 * 128)
#define SM_ATTN_BYTES  (SM_ATTN_FLOATS * 4)

__global__ __launch_bounds__(256, 2)
void attn_kernel(const float* __restrict__ rel,
                 const float* __restrict__ qb,
                 const float* __restrict__ kb,
                 const float* __restrict__ vb,
                 float* __restrict__ ctx)
{
    extern __shared__ float sm[];
    float* sQ   = sm;                  // [64][AP] Q rows (pre-scaled by 1/8)
    float* sV   = sQ + SM_Q;           // [b*64+j][VP]+d tf32 V
    float* sP   = sV + SM_V;           // [row=64][AP] exp'd tf32 probs
    float* sExM = sP + SM_P;           // [8 warps][16 rows] max exchange
    float* sExS = sExM + 128;          // [8 warps][16 rows] sum exchange

    const int i    = blockIdx.x;
    const int tid  = threadIdx.x;
    const int lane = tid & 31;
    const int w    = tid >> 5;
    const int b    = w >> 1;           // batch
    const int half = w & 1;            // j-half (scores) / d-half (AV)
    const int g    = lane >> 2;
    const int t    = lane & 3;
    const unsigned FULL = 0xffffffffu;

    // Load Q for all 64 (b,h) rows at query i, pre-scaled by 1/8
    #pragma unroll
    for (int tix = 0; tix < 16; tix++) {
        const int idx = tix * 256 + tid;
        const int r = idx >> 6, d = idx & 63;
        sQ[r * AP + d] = 0.125f * qb[((size_t)r * SEQ + i) * DH + d];
    }

    // L2-prefetch tile-0 rel (128 x 128B lines)
    if (tid < 128)
        l2_prefetch(&rel[((size_t)i * SEQ + (tid >> 1)) * DH + (tid & 1) * 32]);

    // per-warp running softmax state for rows b*16+g, b*16+g+8
    float mr0 = -INFINITY, mr1 = -INFINITY, lr0 = 0.f, lr1 = 0.f;
    float cacc[4][4];
    #pragma unroll
    for (int nt = 0; nt < 4; nt++)
        #pragma unroll
        for (int q = 0; q < 4; q++) cacc[nt][q] = 0.f;

    for (int j0 = 0; j0 < SEQ; j0 += 64) {
        __syncthreads();   // S0: prev tile's AV reads of sV/sP complete

        // ---- V: gmem [b][j][d] -> sV (rna tf32); overlaps scores below ----
        #pragma unroll
        for (int tix = 0; tix < 4; tix++) {
            const int idx = tix * 256 + tid;
            const int j  = idx >> 4;
            const int d4 = (idx & 15) * 4;
            #pragma unroll
            for (int bb = 0; bb < 4; bb++) {
                const float4 v4 = *(const float4*)&vb[((size_t)(bb * SEQ) + j0 + j) * DH + d4];
                float4 o;
                o.x = f2tf(v4.x); o.y = f2tf(v4.y);
                o.z = f2tf(v4.z); o.w = f2tf(v4.w);
                *(float4*)&sV[(bb * 64 + j) * VP + d4] = o;
            }
        }
        // L2-prefetch next tile's rel
        if (j0 + 64 < SEQ && tid < 128)
            l2_prefetch(&rel[((size_t)i * SEQ + j0 + 64 + (tid >> 1)) * DH + (tid & 1) * 32]);

        // ---- scores MMA with direct-gmem B-fragments: bf = K + rel ----
        float pr[4][4];
        #pragma unroll
        for (int nt = 0; nt < 4; nt++)
            #pragma unroll
            for (int q = 0; q < 4; q++) pr[nt][q] = 0.f;

        {
            // warp-base pointers: row = j0 + half*32 + g (+ nt*8), col = t (+ks*8)
            const float* kwb = kb + ((size_t)(b * SEQ) + j0 + half * 32 + g) * DH + t;
            const float* rwb = rel + ((size_t)i * SEQ + j0 + half * 32 + g) * DH + t;
            #pragma unroll
            for (int ks = 0; ks < 8; ks++) {
                const int k = ks * 8;
                uint32_t af[4];
                af[0] = __float_as_uint(sQ[(b * 16 + g) * AP + k + t]);
                af[1] = __float_as_uint(sQ[(b * 16 + g + 8) * AP + k + t]);
                af[2] = __float_as_uint(sQ[(b * 16 + g) * AP + k + t + 4]);
                af[3] = __float_as_uint(sQ[(b * 16 + g + 8) * AP + k + t + 4]);
                #pragma unroll
                for (int nt = 0; nt < 4; nt++) {
                    const int off = nt * 8 * DH + k;     // compile-time immediate
                    uint32_t bf[2];
                    bf[0] = __float_as_uint(kwb[off]     + rwb[off]);
                    bf[1] = __float_as_uint(kwb[off + 4] + rwb[off + 4]);
                    mma_tf32(pr[nt], af, bf);
                }
            }
        }

        // ---- row max (quad reduce) + cross-half exchange ----
        float m0 = -INFINITY, m1 = -INFINITY;
        #pragma unroll
        for (int nt = 0; nt < 4; nt++) {
            m0 = fmaxf(m0, fmaxf(pr[nt][0], pr[nt][1]));
            m1 = fmaxf(m1, fmaxf(pr[nt][2], pr[nt][3]));
        }
        m0 = fmaxf(m0, __shfl_xor_sync(FULL, m0, 1));
        m0 = fmaxf(m0, __shfl_xor_sync(FULL, m0, 2));
        m1 = fmaxf(m1, __shfl_xor_sync(FULL, m1, 1));
        m1 = fmaxf(m1, __shfl_xor_sync(FULL, m1, 2));
        if (t == 0) {
            sExM[w * 16 + g]     = m0;
            sExM[w * 16 + 8 + g] = m1;
        }
        __syncthreads();   // S1: sExM visible

        const float pm0 = sExM[(w ^ 1) * 16 + g];
        const float pm1 = sExM[(w ^ 1) * 16 + 8 + g];
        const float mn0 = fmaxf(mr0, fmaxf(m0, pm0));
        const float mn1 = fmaxf(mr1, fmaxf(m1, pm1));
        const float corr0 = __expf(mr0 - mn0);
        const float corr1 = __expf(mr1 - mn1);
        mr0 = mn0; mr1 = mn1;

        // ---- exp in registers, single tf32 P write, row sums ----
        float s0 = 0.f, s1 = 0.f;
        #pragma unroll
        for (int nt = 0; nt < 4; nt++) {
            float p0 = __expf(pr[nt][0] - mn0);
            float p1 = __expf(pr[nt][1] - mn0);
            float p2 = __expf(pr[nt][2] - mn1);
            float p3 = __expf(pr[nt][3] - mn1);
            s0 += p0 + p1; s1 += p2 + p3;
            const int jc = half * 32 + nt * 8 + 2 * t;
            *(float2*)&sP[(b * 16 + g) * AP + jc] =
                make_float2(f2tf(p0), f2tf(p1));
            *(float2*)&sP[(b * 16 + g + 8) * AP + jc] =
                make_float2(f2tf(p2), f2tf(p3));
        }
        s0 += __shfl_xor_sync(FULL, s0, 1);
        s0 += __shfl_xor_sync(FULL, s0, 2);
        s1 += __shfl_xor_sync(FULL, s1, 1);
        s1 += __shfl_xor_sync(FULL, s1, 2);
        if (t == 0) {
            sExS[w * 16 + g]     = s0;
            sExS[w * 16 + 8 + g] = s1;
        }
        __syncthreads();   // S2: sP, sV, sExS all published

        lr0 = lr0 * corr0 + s0 + sExS[(w ^ 1) * 16 + g];
        lr1 = lr1 * corr1 + s1 + sExS[(w ^ 1) * 16 + 8 + g];

        // ---- rescale ctx + AV MMA: rows b*16+{g,g+8}, N=32 d (half), K=64 j ----
        #pragma unroll
        for (int nt = 0; nt < 4; nt++) {
            cacc[nt][0] *= corr0; cacc[nt][1] *= corr0;
            cacc[nt][2] *= corr1; cacc[nt][3] *= corr1;
        }
        #pragma unroll
        for (int ks = 0; ks < 8; ks++) {
            const int k = ks * 8;   // j within tile
            uint32_t af[4], bf[2];
            af[0] = __float_as_uint(sP[(b * 16 + g) * AP + k + t]);
            af[1] = __float_as_uint(sP[(b * 16 + g + 8) * AP + k + t]);
            af[2] = __float_as_uint(sP[(b * 16 + g) * AP + k + t + 4]);
            af[3] = __float_as_uint(sP[(b * 16 + g + 8) * AP + k + t + 4]);
            #pragma unroll
            for (int nt = 0; nt < 4; nt++) {
                const int n = half * 32 + nt * 8 + g;   // d column
                bf[0] = __float_as_uint(sV[(b * 64 + k + t) * VP + n]);
                bf[1] = __float_as_uint(sV[(b * 64 + k + t + 4) * VP + n]);
                mma_tf32(cacc[nt], af, bf);
            }
        }
    }

    // ---- epilogue: normalize + write ctx [b][i][h*DH + d] ----
    {
        const float inv0 = 1.f / lr0;
        const float inv1 = 1.f / lr1;
        const size_t base = ((size_t)(b * SEQ) + i) * DM;
        #pragma unroll
        for (int nt = 0; nt < 4; nt++) {
            const int d = half * 32 + nt * 8 + 2 * t;
            *(float2*)&ctx[base + g * DH + d] =
                make_float2(cacc[nt][0] * inv0, cacc[nt][1] * inv0);
            *(float2*)&ctx[base + (g + 8) * DH + d] =
                make_float2(cacc[nt][2] * inv1, cacc[nt][3] * inv1);
        }
    }
}

// ---------------------------------------------------------------------------
extern "C" void kernel_launch(void* const* d_in, const int* in_sizes, int n_in,
                              void* d_out, int out_size)
{
    const float* x   = (const float*)d_in[0];
    const float* rel = (const float*)d_in[1];
    const float* Wq  = (const float*)d_in[2];
    const float* Wk  = (const float*)d_in[3];
    const float* Wv  = (const float*)d_in[4];
    const float* Wo  = (const float*)d_in[5];
    const float* bo  = (const float*)d_in[6];
    float* out = (float*)d_out;

    float *qb, *kb, *vb, *ctx;
    cudaGetSymbolAddress((void**)&qb,  g_q);
    cudaGetSymbolAddress((void**)&kb,  g_k);
    cudaGetSymbolAddress((void**)&vb,  g_v);
    cudaGetSymbolAddress((void**)&ctx, g_ctx);

    cudaFuncSetAttribute(attn_kernel,
                         cudaFuncAttributeMaxDynamicSharedMemorySize,
                         SM_ATTN_BYTES);

    const int M = BATCH * SEQ;  // 4096

    // fused q|k|v projections: blocks x=0..7 -> q (permuted), x=8 -> k,v
    {
        dim3 grid(9, M / 128);
        gemm_tf32<4><<<grid, 256>>>(x, Wq, Wk, Wv, nullptr,
                                    qb, kb, vb, M, DM, DM);
    }
    // fused attention
    attn_kernel<<<SEQ, 256, SM_ATTN_BYTES>>>(rel, qb, kb, vb, ctx);

    // out = ctx @ Wo^T + bo
    {
        dim3 grid(8, M / 128);
        gemm_tf32<2><<<grid, 256>>>(ctx, Wo, nullptr, nullptr, bo,
                                    out, nullptr, nullptr, M, DM, DM);
    }
}

// round 12
// speedup vs baseline: 1.6988x; 1.6988x over previous
#include <cuda_runtime.h>
#include <math.h>
#include <stdint.h>

#define BATCH 4
#define SEQ   1024
#define DM    1024
#define NH    16
#define DH    64

// Scratch (device globals — no allocation allowed)
__device__ float g_q[(size_t)BATCH*NH*SEQ*DH];   // [b*NH+h][s][d]
__device__ float g_k[(size_t)BATCH*SEQ*DH];      // [b*S+s][d]
__device__ float g_v[(size_t)BATCH*SEQ*DH];
__device__ float g_ctx[(size_t)BATCH*SEQ*DM];    // [b*S+s][h*DH+d]

// ---------------------------------------------------------------------------
// TF32 helpers
// ---------------------------------------------------------------------------
__device__ __forceinline__ float f2tf(float x) {
    uint32_t u;
    asm("cvt.rna.tf32.f32 %0, %1;" : "=r"(u) : "f"(x));
    return __uint_as_float(u);
}

__device__ __forceinline__ void mma_tf32(float* c, const uint32_t* a, const uint32_t* b) {
    asm volatile(
        "mma.sync.aligned.m16n8k8.row.col.f32.tf32.tf32.f32 "
        "{%0,%1,%2,%3}, {%4,%5,%6,%7}, {%8,%9}, {%0,%1,%2,%3};\n"
        : "+f"(c[0]), "+f"(c[1]), "+f"(c[2]), "+f"(c[3])
        : "r"(a[0]), "r"(a[1]), "r"(a[2]), "r"(a[3]), "r"(b[0]), "r"(b[1]));
}

__device__ __forceinline__ void l2_prefetch(const void* p) {
    asm volatile("prefetch.global.L2 [%0];" :: "l"(p));
}

// ---------------------------------------------------------------------------
// TF32 GEMM, double-buffered smem (1 barrier per k-iter). (R8, unchanged)
// MODE 2: out = A @ Wo^T + bias
// MODE 4: fused projections: x<8 -> q permuted; x==8 -> k,v.
// ---------------------------------------------------------------------------
#define GP 20

template<int MODE>
__global__ __launch_bounds__(256, 2)
void gemm_tf32(const float* __restrict__ A, const float* __restrict__ B,
               const float* __restrict__ Bk, const float* __restrict__ Bv,
               const float* __restrict__ bias,
               float* __restrict__ C, float* __restrict__ Ck, float* __restrict__ Cv,
               int M, int N, int K)
{
    __shared__ float sA[2][128 * GP];
    __shared__ float sB[2][128 * GP];

    const int tid  = threadIdx.x;
    const int lane = tid & 31;
    const int w    = tid >> 5;
    const int wr   = w >> 1;
    const int wc   = w & 1;
    const int g    = lane >> 2;
    const int t    = lane & 3;
    const int m0   = blockIdx.y * 128;
    const bool kv  = (MODE == 4) && (blockIdx.x == 8);
    const int n0   = kv ? 0 : blockIdx.x * 128;

    const int ldr = tid >> 2;
    const int ldc = (tid & 3) * 4;

    float acc[2][8][4];
    #pragma unroll
    for (int mt = 0; mt < 2; mt++)
        #pragma unroll
        for (int nt = 0; nt < 8; nt++)
            #pragma unroll
            for (int q = 0; q < 4; q++) acc[mt][nt][q] = 0.f;

    float4 ar[2], br[2];

    #pragma unroll
    for (int h = 0; h < 2; h++) {
        const int row = ldr + h * 64;
        ar[h] = *(const float4*)&A[(size_t)(m0 + row) * K + ldc];
        if (MODE == 4 && kv) {
            const float* Bs = (row >= 64) ? Bv : Bk;
            br[h] = *(const float4*)&Bs[(size_t)(row & 63) * K + ldc];
        } else {
            br[h] = *(const float4*)&B[(size_t)(n0 + row) * K + ldc];
        }
    }
    {
        #pragma unroll
        for (int h = 0; h < 2; h++) {
            const int row = ldr + h * 64;
            float* da = &sA[0][row * GP + ldc];
            da[0] = f2tf(ar[h].x); da[1] = f2tf(ar[h].y);
            da[2] = f2tf(ar[h].z); da[3] = f2tf(ar[h].w);
            float* db = &sB[0][row * GP + ldc];
            db[0] = f2tf(br[h].x); db[1] = f2tf(br[h].y);
            db[2] = f2tf(br[h].z); db[3] = f2tf(br[h].w);
        }
        #pragma unroll
        for (int h = 0; h < 2; h++) {
            const int row = ldr + h * 64;
            ar[h] = *(const float4*)&A[(size_t)(m0 + row) * K + 16 + ldc];
            if (MODE == 4 && kv) {
                const float* Bs = (row >= 64) ? Bv : Bk;
                br[h] = *(const float4*)&Bs[(size_t)(row & 63) * K + 16 + ldc];
            } else {
                br[h] = *(const float4*)&B[(size_t)(n0 + row) * K + 16 + ldc];
            }
        }
    }
    __syncthreads();

    const int nIt = K >> 4;
    for (int it = 0; it < nIt; it++) {
        const int buf = it & 1;
        const float* cA = sA[buf];
        const float* cB = sB[buf];

        #pragma unroll
        for (int ks = 0; ks < 2; ks++) {
            const int k = ks * 8;
            uint32_t af[2][4], bf[8][2];
            #pragma unroll
            for (int mt = 0; mt < 2; mt++) {
                const int mr = wr * 32 + mt * 16;
                af[mt][0] = __float_as_uint(cA[(mr + g) * GP + k + t]);
                af[mt][1] = __float_as_uint(cA[(mr + g + 8) * GP + k + t]);
                af[mt][2] = __float_as_uint(cA[(mr + g) * GP + k + t + 4]);
                af[mt][3] = __float_as_uint(cA[(mr + g + 8) * GP + k + t + 4]);
            }
            #pragma unroll
            for (int nt = 0; nt < 8; nt++) {
                const int nn = wc * 64 + nt * 8 + g;
                bf[nt][0] = __float_as_uint(cB[nn * GP + k + t]);
                bf[nt][1] = __float_as_uint(cB[nn * GP + k + t + 4]);
            }
            #pragma unroll
            for (int mt = 0; mt < 2; mt++)
                #pragma unroll
                for (int nt = 0; nt < 8; nt++)
                    mma_tf32(acc[mt][nt], af[mt], bf[nt]);
        }

        if (it + 1 < nIt) {
            float* dA = sA[buf ^ 1];
            float* dB = sB[buf ^ 1];
            #pragma unroll
            for (int h = 0; h < 2; h++) {
                const int row = ldr + h * 64;
                float* da = &dA[row * GP + ldc];
                da[0] = f2tf(ar[h].x); da[1] = f2tf(ar[h].y);
                da[2] = f2tf(ar[h].z); da[3] = f2tf(ar[h].w);
                float* db = &dB[row * GP + ldc];
                db[0] = f2tf(br[h].x); db[1] = f2tf(br[h].y);
                db[2] = f2tf(br[h].z); db[3] = f2tf(br[h].w);
            }
            if (it + 2 < nIt) {
                const int k0 = (it + 2) * 16;
                #pragma unroll
                for (int h = 0; h < 2; h++) {
                    const int row = ldr + h * 64;
                    ar[h] = *(const float4*)&A[(size_t)(m0 + row) * K + k0 + ldc];
                    if (MODE == 4 && kv) {
                        const float* Bs = (row >= 64) ? Bv : Bk;
                        br[h] = *(const float4*)&Bs[(size_t)(row & 63) * K + k0 + ldc];
                    } else {
                        br[h] = *(const float4*)&B[(size_t)(n0 + row) * K + k0 + ldc];
                    }
                }
            }
        }
        __syncthreads();
    }

    #pragma unroll
    for (int mt = 0; mt < 2; mt++) {
        #pragma unroll
        for (int rr = 0; rr < 2; rr++) {
            const int m = m0 + wr * 32 + mt * 16 + g + rr * 8;
            #pragma unroll
            for (int nt = 0; nt < 8; nt++) {
                const int n = n0 + wc * 64 + nt * 8 + 2 * t;
                const float v0 = acc[mt][nt][rr * 2 + 0];
                const float v1 = acc[mt][nt][rr * 2 + 1];
                if (MODE == 2) {
                    *(float2*)&C[(size_t)m * N + n] =
                        make_float2(v0 + bias[n], v1 + bias[n + 1]);
                } else if (MODE == 4 && !kv) {
                    const int b = m >> 10, s = m & 1023;
                    const int h = n >> 6, d = n & 63;
                    *(float2*)&C[(((size_t)(b * NH + h)) * SEQ + s) * DH + d] =
                        make_float2(v0, v1);
                } else {
                    float* dst = wc ? Cv : Ck;
                    const int nn = nt * 8 + 2 * t;
                    *(float2*)&dst[(size_t)m * 64 + nn] = make_float2(v0, v1);
                }
            }
        }
    }
}

// ---------------------------------------------------------------------------
// Fused attention v4: CTA fission. One CTA per (query i, batch b):
// grid 4096, 64 threads (2 warps = the R8 (b,half) pair). Same math,
// layouts, and per-warp work as R8 — but barriers now couple only 2 warps,
// and 8 independent CTAs/SM hide each other's stalls.
// ---------------------------------------------------------------------------
#define AP 68   // pitch for sQ / sKR / sP
#define VP 72   // pitch for V rows (72 % 32 == 8 -> AV B-frag conflict-free)

#define SM_Q   (16 * AP)
#define SM_KV  (64 * VP)               // KR at pitch AP / V at pitch VP
#define SM_P   (16 * AP)
#define SM_ATTN_FLOATS (SM_Q + SM_KV + SM_P + 2 * 32)
#define SM_ATTN_BYTES  (SM_ATTN_FLOATS * 4)

__global__ __launch_bounds__(64, 8)
void attn_kernel(const float* __restrict__ rel,
                 const float* __restrict__ qb,
                 const float* __restrict__ kb,
                 const float* __restrict__ vb,
                 float* __restrict__ ctx)
{
    extern __shared__ float sm[];
    float* sQ   = sm;                  // [16][AP] Q rows (pre-scaled by 1/8)
    float* sKV  = sQ + SM_Q;           // KR: [j][AP]+d ; V: [j][VP]+d
    float* sP   = sKV + SM_KV;         // [16][AP] exp'd tf32 probs
    float* sExM = sP + SM_P;           // [2 warps][16 rows] max exchange
    float* sExS = sExM + 32;           // [2 warps][16 rows] sum exchange

    const int bid  = blockIdx.x;
    const int i    = bid >> 2;         // query index
    const int b    = bid & 3;          // batch
    const int tid  = threadIdx.x;      // 0..63
    const int lane = tid & 31;
    const int w    = tid >> 5;         // warp 0/1
    const int half = w;                // j-half (scores) / d-half (AV)
    const int g    = lane >> 2;
    const int t    = lane & 3;
    const unsigned FULL = 0xffffffffu;

    // Load Q rows (16 heads of batch b at query i), pre-scaled by 1/8
    #pragma unroll
    for (int tix = 0; tix < 4; tix++) {
        const int idx = tix * 64 + tid;         // 256 quads
        const int r  = idx >> 4;                // head 0..15
        const int d4 = (idx & 15) * 4;
        const float4 q4 =
            *(const float4*)&qb[(((size_t)(b * NH + r)) * SEQ + i) * DH + d4];
        float4 o;
        o.x = 0.125f * q4.x; o.y = 0.125f * q4.y;
        o.z = 0.125f * q4.z; o.w = 0.125f * q4.w;
        *(float4*)&sQ[r * AP + d4] = o;
    }

    // L2-prefetch tile-0 rel
    {
        const int j = tid >> 1, c = (tid & 1) * 32;
        l2_prefetch(&rel[((size_t)i * SEQ + j) * DH + c]);
        l2_prefetch(&rel[((size_t)i * SEQ + 32 + j) * DH + c]);
    }

    // per-warp running softmax state for rows g and g+8
    float mr0 = -INFINITY, mr1 = -INFINITY, lr0 = 0.f, lr1 = 0.f;
    float cacc[4][4];
    #pragma unroll
    for (int nt = 0; nt < 4; nt++)
        #pragma unroll
        for (int q = 0; q < 4; q++) cacc[nt][q] = 0.f;

    for (int j0 = 0; j0 < SEQ; j0 += 64) {
        __syncthreads();   // S0: prev tile's AV reads of sKV/sP complete

        // ---- build KR[j][d] = K + rel (fp32; MMA truncates) ----
        #pragma unroll 4
        for (int tix = 0; tix < 16; tix++) {
            const int idx = tix * 64 + tid;     // 1024 quads: 64j x 16 dq
            const int j  = idx >> 4;
            const int d4 = (idx & 15) * 4;
            const float4 rv = *(const float4*)&rel[((size_t)i * SEQ + j0 + j) * DH + d4];
            const float4 k4 = *(const float4*)&kb[((size_t)(b * SEQ) + j0 + j) * DH + d4];
            float4 o;
            o.x = k4.x + rv.x; o.y = k4.y + rv.y;
            o.z = k4.z + rv.z; o.w = k4.w + rv.w;
            *(float4*)&sKV[j * AP + d4] = o;
        }
        __syncthreads();   // S1

        // L2-prefetch next tile's rel (overlaps scores MMA)
        if (j0 + 64 < SEQ) {
            const int j = tid >> 1, c = (tid & 1) * 32;
            l2_prefetch(&rel[((size_t)i * SEQ + j0 + 64 + j) * DH + c]);
            l2_prefetch(&rel[((size_t)i * SEQ + j0 + 96 + j) * DH + c]);
        }

        // ---- scores MMA: rows {g,g+8}, cols half*32 + nt*8 + {2t,2t+1} ----
        float pr[4][4];
        #pragma unroll
        for (int nt = 0; nt < 4; nt++)
            #pragma unroll
            for (int q = 0; q < 4; q++) pr[nt][q] = 0.f;

        #pragma unroll
        for (int ks = 0; ks < 8; ks++) {
            const int k = ks * 8;
            uint32_t af[4], bf[2];
            af[0] = __float_as_uint(sQ[g * AP + k + t]);
            af[1] = __float_as_uint(sQ[(g + 8) * AP + k + t]);
            af[2] = __float_as_uint(sQ[g * AP + k + t + 4]);
            af[3] = __float_as_uint(sQ[(g + 8) * AP + k + t + 4]);
            #pragma unroll
            for (int nt = 0; nt < 4; nt++) {
                const int n = half * 32 + nt * 8 + g;
                bf[0] = __float_as_uint(sKV[n * AP + k + t]);
                bf[1] = __float_as_uint(sKV[n * AP + k + t + 4]);
                mma_tf32(pr[nt], af, bf);
            }
        }

        // ---- row max (quad reduce) + cross-warp exchange ----
        float m0 = -INFINITY, m1 = -INFINITY;
        #pragma unroll
        for (int nt = 0; nt < 4; nt++) {
            m0 = fmaxf(m0, fmaxf(pr[nt][0], pr[nt][1]));
            m1 = fmaxf(m1, fmaxf(pr[nt][2], pr[nt][3]));
        }
        m0 = fmaxf(m0, __shfl_xor_sync(FULL, m0, 1));
        m0 = fmaxf(m0, __shfl_xor_sync(FULL, m0, 2));
        m1 = fmaxf(m1, __shfl_xor_sync(FULL, m1, 1));
        m1 = fmaxf(m1, __shfl_xor_sync(FULL, m1, 2));
        if (t == 0) {
            sExM[w * 16 + g]     = m0;
            sExM[w * 16 + 8 + g] = m1;
        }
        __syncthreads();   // S2: sExM visible; KR reads done -> V may overwrite

        const float pm0 = sExM[(w ^ 1) * 16 + g];
        const float pm1 = sExM[(w ^ 1) * 16 + 8 + g];
        const float mn0 = fmaxf(mr0, fmaxf(m0, pm0));
        const float mn1 = fmaxf(mr1, fmaxf(m1, pm1));
        const float corr0 = __expf(mr0 - mn0);
        const float corr1 = __expf(mr1 - mn1);
        mr0 = mn0; mr1 = mn1;

        // ---- exp in registers, single tf32 P write, row sums ----
        float s0 = 0.f, s1 = 0.f;
        #pragma unroll
        for (int nt = 0; nt < 4; nt++) {
            float p0 = __expf(pr[nt][0] - mn0);
            float p1 = __expf(pr[nt][1] - mn0);
            float p2 = __expf(pr[nt][2] - mn1);
            float p3 = __expf(pr[nt][3] - mn1);
            s0 += p0 + p1; s1 += p2 + p3;
            const int jc = half * 32 + nt * 8 + 2 * t;
            *(float2*)&sP[g * AP + jc]       = make_float2(f2tf(p0), f2tf(p1));
            *(float2*)&sP[(g + 8) * AP + jc] = make_float2(f2tf(p2), f2tf(p3));
        }
        s0 += __shfl_xor_sync(FULL, s0, 1);
        s0 += __shfl_xor_sync(FULL, s0, 2);
        s1 += __shfl_xor_sync(FULL, s1, 1);
        s1 += __shfl_xor_sync(FULL, s1, 2);
        if (t == 0) {
            sExS[w * 16 + g]     = s0;
            sExS[w * 16 + 8 + g] = s1;
        }

        // ---- V: gmem [j][d] -> sKV[j][VP]+d (rna tf32, float4) ----
        #pragma unroll 4
        for (int tix = 0; tix < 16; tix++) {
            const int idx = tix * 64 + tid;
            const int j  = idx >> 4;
            const int d4 = (idx & 15) * 4;
            const float4 v4 = *(const float4*)&vb[((size_t)(b * SEQ) + j0 + j) * DH + d4];
            float4 o;
            o.x = f2tf(v4.x); o.y = f2tf(v4.y);
            o.z = f2tf(v4.z); o.w = f2tf(v4.w);
            *(float4*)&sKV[j * VP + d4] = o;
        }
        __syncthreads();   // S3: sP, sKV(V), sExS ready

        lr0 = lr0 * corr0 + s0 + sExS[(w ^ 1) * 16 + g];
        lr1 = lr1 * corr1 + s1 + sExS[(w ^ 1) * 16 + 8 + g];

        // ---- rescale ctx + AV MMA: rows {g,g+8}, N=32 d (half), K=64 j ----
        #pragma unroll
        for (int nt = 0; nt < 4; nt++) {
            cacc[nt][0] *= corr0; cacc[nt][1] *= corr0;
            cacc[nt][2] *= corr1; cacc[nt][3] *= corr1;
        }
        #pragma unroll
        for (int ks = 0; ks < 8; ks++) {
            const int k = ks * 8;   // j within tile
            uint32_t af[4], bf[2];
            af[0] = __float_as_uint(sP[g * AP + k + t]);
            af[1] = __float_as_uint(sP[(g + 8) * AP + k + t]);
            af[2] = __float_as_uint(sP[g * AP + k + t + 4]);
            af[3] = __float_as_uint(sP[(g + 8) * AP + k + t + 4]);
            #pragma unroll
            for (int nt = 0; nt < 4; nt++) {
                const int n = half * 32 + nt * 8 + g;   // d column
                bf[0] = __float_as_uint(sKV[(k + t) * VP + n]);
                bf[1] = __float_as_uint(sKV[(k + t + 4) * VP + n]);
                mma_tf32(cacc[nt], af, bf);
            }
        }
    }

    // ---- epilogue: normalize + write ctx [b][i][h*DH + d] ----
    {
        const float inv0 = 1.f / lr0;
        const float inv1 = 1.f / lr1;
        const size_t base = ((size_t)(b * SEQ) + i) * DM;
        #pragma unroll
        for (int nt = 0; nt < 4; nt++) {
            const int d = half * 32 + nt * 8 + 2 * t;
            *(float2*)&ctx[base + g * DH + d] =
                make_float2(cacc[nt][0] * inv0, cacc[nt][1] * inv0);
            *(float2*)&ctx[base + (g + 8) * DH + d] =
                make_float2(cacc[nt][2] * inv1, cacc[nt][3] * inv1);
        }
    }
}

// ---------------------------------------------------------------------------
extern "C" void kernel_launch(void* const* d_in, const int* in_sizes, int n_in,
                              void* d_out, int out_size)
{
    const float* x   = (const float*)d_in[0];
    const float* rel = (const float*)d_in[1];
    const float* Wq  = (const float*)d_in[2];
    const float* Wk  = (const float*)d_in[3];
    const float* Wv  = (const float*)d_in[4];
    const float* Wo  = (const float*)d_in[5];
    const float* bo  = (const float*)d_in[6];
    float* out = (float*)d_out;

    float *qb, *kb, *vb, *ctx;
    cudaGetSymbolAddress((void**)&qb,  g_q);
    cudaGetSymbolAddress((void**)&kb,  g_k);
    cudaGetSymbolAddress((void**)&vb,  g_v);
    cudaGetSymbolAddress((void**)&ctx, g_ctx);

    cudaFuncSetAttribute(attn_kernel,
                         cudaFuncAttributeMaxDynamicSharedMemorySize,
                         SM_ATTN_BYTES);

    const int M = BATCH * SEQ;  // 4096

    // fused q|k|v projections: blocks x=0..7 -> q (permuted), x=8 -> k,v
    {
        dim3 grid(9, M / 128);
        gemm_tf32<4><<<grid, 256>>>(x, Wq, Wk, Wv, nullptr,
                                    qb, kb, vb, M, DM, DM);
    }
    // fused attention: one CTA per (query i, batch b)
    attn_kernel<<<SEQ * BATCH, 64, SM_ATTN_BYTES>>>(rel, qb, kb, vb, ctx);

    // out = ctx @ Wo^T + bo
    {
        dim3 grid(8, M / 128);
        gemm_tf32<2><<<grid, 256>>>(ctx, Wo, nullptr, nullptr, bo,
                                    out, nullptr, nullptr, M, DM, DM);
    }
}

// round 13
// speedup vs baseline: 2.3071x; 1.3581x over previous
#include <cuda_runtime.h>
#include <cuda_fp16.h>
#include <math.h>
#include <stdint.h>

#define BATCH 4
#define SEQ   1024
#define DM    1024
#define NH    16
#define DH    64

// Scratch (device globals — no allocation allowed)
__device__ float g_q[(size_t)BATCH*NH*SEQ*DH];   // [b*NH+h][s][d]
__device__ float g_k[(size_t)BATCH*SEQ*DH];      // [b*S+s][d]
__device__ float g_v[(size_t)BATCH*SEQ*DH];      // used as V^T: [d][b*S+j]
__device__ float g_ctx[(size_t)BATCH*SEQ*DM];    // [b*S+s][h*DH+d]

// ---------------------------------------------------------------------------
// helpers
// ---------------------------------------------------------------------------
__device__ __forceinline__ float f2tf(float x) {
    uint32_t u;
    asm("cvt.rna.tf32.f32 %0, %1;" : "=r"(u) : "f"(x));
    return __uint_as_float(u);
}

__device__ __forceinline__ uint32_t f2h2(float a, float b) {
    __half2 h = __floats2half2_rn(a, b);
    return *(uint32_t*)&h;
}

__device__ __forceinline__ void mma_tf32(float* c, const uint32_t* a, const uint32_t* b) {
    asm volatile(
        "mma.sync.aligned.m16n8k8.row.col.f32.tf32.tf32.f32 "
        "{%0,%1,%2,%3}, {%4,%5,%6,%7}, {%8,%9}, {%0,%1,%2,%3};\n"
        : "+f"(c[0]), "+f"(c[1]), "+f"(c[2]), "+f"(c[3])
        : "r"(a[0]), "r"(a[1]), "r"(a[2]), "r"(a[3]), "r"(b[0]), "r"(b[1]));
}

__device__ __forceinline__ void mma_f16(float* c, const uint32_t* a, const uint32_t* b) {
    asm volatile(
        "mma.sync.aligned.m16n8k16.row.col.f32.f16.f16.f32 "
        "{%0,%1,%2,%3}, {%4,%5,%6,%7}, {%8,%9}, {%0,%1,%2,%3};\n"
        : "+f"(c[0]), "+f"(c[1]), "+f"(c[2]), "+f"(c[3])
        : "r"(a[0]), "r"(a[1]), "r"(a[2]), "r"(a[3]), "r"(b[0]), "r"(b[1]));
}

// ---------------------------------------------------------------------------
// TF32 GEMM, double-buffered smem (R8). MODE 2: out = A@Wo^T + bias.
// MODE 4: fused projections; x<8 -> q permuted; x==8 -> k + v-TRANSPOSED.
// ---------------------------------------------------------------------------
#define GP 20

template<int MODE>
__global__ __launch_bounds__(256, 2)
void gemm_tf32(const float* __restrict__ A, const float* __restrict__ B,
               const float* __restrict__ Bk, const float* __restrict__ Bv,
               const float* __restrict__ bias,
               float* __restrict__ C, float* __restrict__ Ck, float* __restrict__ Cv,
               int M, int N, int K)
{
    __shared__ float sA[2][128 * GP];
    __shared__ float sB[2][128 * GP];

    const int tid  = threadIdx.x;
    const int lane = tid & 31;
    const int w    = tid >> 5;
    const int wr   = w >> 1;
    const int wc   = w & 1;
    const int g    = lane >> 2;
    const int t    = lane & 3;
    const int m0   = blockIdx.y * 128;
    const bool kv  = (MODE == 4) && (blockIdx.x == 8);
    const int n0   = kv ? 0 : blockIdx.x * 128;

    const int ldr = tid >> 2;
    const int ldc = (tid & 3) * 4;

    float acc[2][8][4];
    #pragma unroll
    for (int mt = 0; mt < 2; mt++)
        #pragma unroll
        for (int nt = 0; nt < 8; nt++)
            #pragma unroll
            for (int q = 0; q < 4; q++) acc[mt][nt][q] = 0.f;

    float4 ar[2], br[2];

    #pragma unroll
    for (int h = 0; h < 2; h++) {
        const int row = ldr + h * 64;
        ar[h] = *(const float4*)&A[(size_t)(m0 + row) * K + ldc];
        if (MODE == 4 && kv) {
            const float* Bs = (row >= 64) ? Bv : Bk;
            br[h] = *(const float4*)&Bs[(size_t)(row & 63) * K + ldc];
        } else {
            br[h] = *(const float4*)&B[(size_t)(n0 + row) * K + ldc];
        }
    }
    {
        #pragma unroll
        for (int h = 0; h < 2; h++) {
            const int row = ldr + h * 64;
            float* da = &sA[0][row * GP + ldc];
            da[0] = f2tf(ar[h].x); da[1] = f2tf(ar[h].y);
            da[2] = f2tf(ar[h].z); da[3] = f2tf(ar[h].w);
            float* db = &sB[0][row * GP + ldc];
            db[0] = f2tf(br[h].x); db[1] = f2tf(br[h].y);
            db[2] = f2tf(br[h].z); db[3] = f2tf(br[h].w);
        }
        #pragma unroll
        for (int h = 0; h < 2; h++) {
            const int row = ldr + h * 64;
            ar[h] = *(const float4*)&A[(size_t)(m0 + row) * K + 16 + ldc];
            if (MODE == 4 && kv) {
                const float* Bs = (row >= 64) ? Bv : Bk;
                br[h] = *(const float4*)&Bs[(size_t)(row & 63) * K + 16 + ldc];
            } else {
                br[h] = *(const float4*)&B[(size_t)(n0 + row) * K + 16 + ldc];
            }
        }
    }
    __syncthreads();

    const int nIt = K >> 4;
    for (int it = 0; it < nIt; it++) {
        const int buf = it & 1;
        const float* cA = sA[buf];
        const float* cB = sB[buf];

        #pragma unroll
        for (int ks = 0; ks < 2; ks++) {
            const int k = ks * 8;
            uint32_t af[2][4], bf[8][2];
            #pragma unroll
            for (int mt = 0; mt < 2; mt++) {
                const int mr = wr * 32 + mt * 16;
                af[mt][0] = __float_as_uint(cA[(mr + g) * GP + k + t]);
                af[mt][1] = __float_as_uint(cA[(mr + g + 8) * GP + k + t]);
                af[mt][2] = __float_as_uint(cA[(mr + g) * GP + k + t + 4]);
                af[mt][3] = __float_as_uint(cA[(mr + g + 8) * GP + k + t + 4]);
            }
            #pragma unroll
            for (int nt = 0; nt < 8; nt++) {
                const int nn = wc * 64 + nt * 8 + g;
                bf[nt][0] = __float_as_uint(cB[nn * GP + k + t]);
                bf[nt][1] = __float_as_uint(cB[nn * GP + k + t + 4]);
            }
            #pragma unroll
            for (int mt = 0; mt < 2; mt++)
                #pragma unroll
                for (int nt = 0; nt < 8; nt++)
                    mma_tf32(acc[mt][nt], af[mt], bf[nt]);
        }

        if (it + 1 < nIt) {
            float* dA = sA[buf ^ 1];
            float* dB = sB[buf ^ 1];
            #pragma unroll
            for (int h = 0; h < 2; h++) {
                const int row = ldr + h * 64;
                float* da = &dA[row * GP + ldc];
                da[0] = f2tf(ar[h].x); da[1] = f2tf(ar[h].y);
                da[2] = f2tf(ar[h].z); da[3] = f2tf(ar[h].w);
                float* db = &dB[row * GP + ldc];
                db[0] = f2tf(br[h].x); db[1] = f2tf(br[h].y);
                db[2] = f2tf(br[h].z); db[3] = f2tf(br[h].w);
            }
            if (it + 2 < nIt) {
                const int k0 = (it + 2) * 16;
                #pragma unroll
                for (int h = 0; h < 2; h++) {
                    const int row = ldr + h * 64;
                    ar[h] = *(const float4*)&A[(size_t)(m0 + row) * K + k0 + ldc];
                    if (MODE == 4 && kv) {
                        const float* Bs = (row >= 64) ? Bv : Bk;
                        br[h] = *(const float4*)&Bs[(size_t)(row & 63) * K + k0 + ldc];
                    } else {
                        br[h] = *(const float4*)&B[(size_t)(n0 + row) * K + k0 + ldc];
                    }
                }
            }
        }
        __syncthreads();
    }

    #pragma unroll
    for (int mt = 0; mt < 2; mt++) {
        #pragma unroll
        for (int rr = 0; rr < 2; rr++) {
            const int m = m0 + wr * 32 + mt * 16 + g + rr * 8;
            #pragma unroll
            for (int nt = 0; nt < 8; nt++) {
                const int n = n0 + wc * 64 + nt * 8 + 2 * t;
                const float v0 = acc[mt][nt][rr * 2 + 0];
                const float v1 = acc[mt][nt][rr * 2 + 1];
                if (MODE == 2) {
                    *(float2*)&C[(size_t)m * N + n] =
                        make_float2(v0 + bias[n], v1 + bias[n + 1]);
                } else if (MODE == 4 && !kv) {
                    const int b = m >> 10, s = m & 1023;
                    const int h = n >> 6, d = n & 63;
                    *(float2*)&C[(((size_t)(b * NH + h)) * SEQ + s) * DH + d] =
                        make_float2(v0, v1);
                } else {
                    const int nn = nt * 8 + 2 * t;
                    if (!wc) {
                        // k: [m][64]
                        *(float2*)&Ck[(size_t)m * 64 + nn] = make_float2(v0, v1);
                    } else {
                        // v TRANSPOSED: [d][m] (m = b*S + j)
                        Cv[(size_t)nn * 4096 + m]       = v0;
                        Cv[(size_t)(nn + 1) * 4096 + m] = v1;
                    }
                }
            }
        }
    }
}

// ---------------------------------------------------------------------------
// Fused attention (R8 structure) in FP16 MMA (m16n8k16):
// half the MMAs and fragment loads, half the smem. V read pre-transposed
// from gmem. All pitches 36 u32 (==4 mod 32 -> conflict-free frags).
// One CTA per query i; 8 warps = (batch, half); 2 CTAs/SM.
// ---------------------------------------------------------------------------
#define QP 36   // pitch in u32 (half2) units

#define SMU_Q   (64 * QP)
#define SMU_KV  (256 * QP)     // KR rows [b*64+j] / V^T rows [b*64+d], time-shared
#define SMU_P   (64 * QP)
#define SMU_TOT (SMU_Q + SMU_KV + SMU_P + 256)
#define SM_ATTN_BYTES (SMU_TOT * 4)

__global__ __launch_bounds__(256, 2)
void attn_kernel(const float* __restrict__ rel,
                 const float* __restrict__ qb,
                 const float* __restrict__ kb,
                 const float* __restrict__ vt,   // V^T [64][4096]
                 float* __restrict__ ctx)
{
    extern __shared__ uint32_t smu[];
    uint32_t* sQ   = smu;                    // [64][QP] half2 Q (pre-scaled)
    uint32_t* sKV  = sQ + SMU_Q;             // KR/V^T half2
    uint32_t* sP   = sKV + SMU_KV;           // [64][QP] half2 probs
    float*    sExM = (float*)(sP + SMU_P);   // [8 warps][16 rows]
    float*    sExS = sExM + 128;

    const int i    = blockIdx.x;
    const int tid  = threadIdx.x;
    const int lane = tid & 31;
    const int w    = tid >> 5;
    const int b    = w >> 1;           // batch
    const int half = w & 1;            // j-half (scores) / d-half (AV)
    const int g    = lane >> 2;
    const int t    = lane & 3;
    const unsigned FULL = 0xffffffffu;

    // Load Q (64 rows x 64 d) -> half2, pre-scaled by 1/8
    #pragma unroll
    for (int tix = 0; tix < 8; tix++) {
        const int idx = tix * 256 + tid;   // 2048 half2
        const int r  = idx >> 5;
        const int dq = idx & 31;
        const float2 q2 = *(const float2*)&qb[((size_t)r * SEQ + i) * DH + 2 * dq];
        sQ[r * QP + dq] = f2h2(0.125f * q2.x, 0.125f * q2.y);
    }

    // prologue: prefetch tile-0 rel into registers
    float4 relbuf[4];
    #pragma unroll
    for (int tix = 0; tix < 4; tix++) {
        const int idx = tix * 256 + tid;
        const int j  = idx >> 4;
        const int d4 = (idx & 15) * 4;
        relbuf[tix] = *(const float4*)&rel[((size_t)i * SEQ + j) * DH + d4];
    }

    // per-warp running softmax state for rows b*16+g, b*16+g+8
    float mr0 = -INFINITY, mr1 = -INFINITY, lr0 = 0.f, lr1 = 0.f;
    float cacc[4][4];
    #pragma unroll
    for (int nt = 0; nt < 4; nt++)
        #pragma unroll
        for (int q = 0; q < 4; q++) cacc[nt][q] = 0.f;

    for (int j0 = 0; j0 < SEQ; j0 += 64) {
        __syncthreads();   // S0: prev tile's AV reads of sKV/sP complete

        // ---- build KR[b][j][d] = half2(K + rel), rna ----
        #pragma unroll
        for (int tix = 0; tix < 4; tix++) {
            const int idx = tix * 256 + tid;
            const int j  = idx >> 4;
            const int d4 = (idx & 15) * 4;
            const int dq = d4 >> 1;
            const float4 rv = relbuf[tix];
            #pragma unroll
            for (int bb = 0; bb < 4; bb++) {
                const float4 k4 = *(const float4*)&kb[((size_t)(bb * SEQ) + j0 + j) * DH + d4];
                const uint32_t h0 = f2h2(k4.x + rv.x, k4.y + rv.y);
                const uint32_t h1 = f2h2(k4.z + rv.z, k4.w + rv.w);
                *(uint2*)&sKV[(bb * 64 + j) * QP + dq] = make_uint2(h0, h1);
            }
        }
        __syncthreads();   // S1

        // prefetch next tile's rel (hidden behind MMA)
        if (j0 + 64 < SEQ) {
            #pragma unroll
            for (int tix = 0; tix < 4; tix++) {
                const int idx = tix * 256 + tid;
                const int j  = idx >> 4;
                const int d4 = (idx & 15) * 4;
                relbuf[tix] =
                    *(const float4*)&rel[((size_t)i * SEQ + j0 + 64 + j) * DH + d4];
            }
        }

        // ---- scores MMA (f16 k16): rows b*16+{g,g+8}, cols half*32+nt*8+{2t,2t+1}
        float pr[4][4];
        #pragma unroll
        for (int nt = 0; nt < 4; nt++)
            #pragma unroll
            for (int q = 0; q < 4; q++) pr[nt][q] = 0.f;

        #pragma unroll
        for (int ks = 0; ks < 4; ks++) {
            const int kq = ks * 8;   // half2 index of k-chunk
            uint32_t af[4], bf[2];
            af[0] = sQ[(b * 16 + g) * QP + kq + t];
            af[1] = sQ[(b * 16 + g + 8) * QP + kq + t];
            af[2] = sQ[(b * 16 + g) * QP + kq + t + 4];
            af[3] = sQ[(b * 16 + g + 8) * QP + kq + t + 4];
            #pragma unroll
            for (int nt = 0; nt < 4; nt++) {
                const int n = half * 32 + nt * 8 + g;
                bf[0] = sKV[(b * 64 + n) * QP + kq + t];
                bf[1] = sKV[(b * 64 + n) * QP + kq + t + 4];
                mma_f16(pr[nt], af, bf);
            }
        }

        // ---- row max (quad reduce) + cross-half exchange ----
        float m0 = -INFINITY, m1 = -INFINITY;
        #pragma unroll
        for (int nt = 0; nt < 4; nt++) {
            m0 = fmaxf(m0, fmaxf(pr[nt][0], pr[nt][1]));
            m1 = fmaxf(m1, fmaxf(pr[nt][2], pr[nt][3]));
        }
        m0 = fmaxf(m0, __shfl_xor_sync(FULL, m0, 1));
        m0 = fmaxf(m0, __shfl_xor_sync(FULL, m0, 2));
        m1 = fmaxf(m1, __shfl_xor_sync(FULL, m1, 1));
        m1 = fmaxf(m1, __shfl_xor_sync(FULL, m1, 2));
        if (t == 0) {
            sExM[w * 16 + g]     = m0;
            sExM[w * 16 + 8 + g] = m1;
        }
        __syncthreads();   // S2: sExM ready; KR reads done -> V may overwrite

        const float pm0 = sExM[(w ^ 1) * 16 + g];
        const float pm1 = sExM[(w ^ 1) * 16 + 8 + g];
        const float mn0 = fmaxf(mr0, fmaxf(m0, pm0));
        const float mn1 = fmaxf(mr1, fmaxf(m1, pm1));
        const float corr0 = __expf(mr0 - mn0);
        const float corr1 = __expf(mr1 - mn1);
        mr0 = mn0; mr1 = mn1;

        // ---- exp in registers, single half2 P write, row sums ----
        float s0 = 0.f, s1 = 0.f;
        #pragma unroll
        for (int nt = 0; nt < 4; nt++) {
            float p0 = __expf(pr[nt][0] - mn0);
            float p1 = __expf(pr[nt][1] - mn0);
            float p2 = __expf(pr[nt][2] - mn1);
            float p3 = __expf(pr[nt][3] - mn1);
            s0 += p0 + p1; s1 += p2 + p3;
            const int jq = half * 16 + nt * 4 + t;   // half2 index of cols 2t,2t+1
            sP[(b * 16 + g) * QP + jq]     = f2h2(p0, p1);
            sP[(b * 16 + g + 8) * QP + jq] = f2h2(p2, p3);
        }
        s0 += __shfl_xor_sync(FULL, s0, 1);
        s0 += __shfl_xor_sync(FULL, s0, 2);
        s1 += __shfl_xor_sync(FULL, s1, 1);
        s1 += __shfl_xor_sync(FULL, s1, 2);
        if (t == 0) {
            sExS[w * 16 + g]     = s0;
            sExS[w * 16 + 8 + g] = s1;
        }

        // ---- V^T: gmem [d][b*S+j] -> sKV[b*64+d][jq] half2 (coalesced) ----
        #pragma unroll
        for (int tix = 0; tix < 4; tix++) {
            const int idx = tix * 256 + tid;
            const int d  = idx >> 4;
            const int j4 = (idx & 15) * 4;
            const int jq = j4 >> 1;
            #pragma unroll
            for (int bb = 0; bb < 4; bb++) {
                const float4 v4 =
                    *(const float4*)&vt[(size_t)d * 4096 + bb * 1024 + j0 + j4];
                *(uint2*)&sKV[(bb * 64 + d) * QP + jq] =
                    make_uint2(f2h2(v4.x, v4.y), f2h2(v4.z, v4.w));
            }
        }
        __syncthreads();   // S3: sP, sKV(V^T), sExS ready

        lr0 = lr0 * corr0 + s0 + sExS[(w ^ 1) * 16 + g];
        lr1 = lr1 * corr1 + s1 + sExS[(w ^ 1) * 16 + 8 + g];

        // ---- rescale ctx + AV MMA (f16 k16): N=32 d (half), K=64 j ----
        #pragma unroll
        for (int nt = 0; nt < 4; nt++) {
            cacc[nt][0] *= corr0; cacc[nt][1] *= corr0;
            cacc[nt][2] *= corr1; cacc[nt][3] *= corr1;
        }
        #pragma unroll
        for (int ks = 0; ks < 4; ks++) {
            const int kq = ks * 8;   // half2 index along j
            uint32_t af[4], bf[2];
            af[0] = sP[(b * 16 + g) * QP + kq + t];
            af[1] = sP[(b * 16 + g + 8) * QP + kq + t];
            af[2] = sP[(b * 16 + g) * QP + kq + t + 4];
            af[3] = sP[(b * 16 + g + 8) * QP + kq + t + 4];
            #pragma unroll
            for (int nt = 0; nt < 4; nt++) {
                const int n = half * 32 + nt * 8 + g;   // d column
                bf[0] = sKV[(b * 64 + n) * QP + kq + t];
                bf[1] = sKV[(b * 64 + n) * QP + kq + t + 4];
                mma_f16(cacc[nt], af, bf);
            }
        }
    }

    // ---- epilogue: normalize + write ctx [b][i][h*DH + d] ----
    {
        const float inv0 = 1.f / lr0;
        const float inv1 = 1.f / lr1;
        const size_t base = ((size_t)(b * SEQ) + i) * DM;
        #pragma unroll
        for (int nt = 0; nt < 4; nt++) {
            const int d = half * 32 + nt * 8 + 2 * t;
            *(float2*)&ctx[base + g * DH + d] =
                make_float2(cacc[nt][0] * inv0, cacc[nt][1] * inv0);
            *(float2*)&ctx[base + (g + 8) * DH + d] =
                make_float2(cacc[nt][2] * inv1, cacc[nt][3] * inv1);
        }
    }
}

// ---------------------------------------------------------------------------
extern "C" void kernel_launch(void* const* d_in, const int* in_sizes, int n_in,
                              void* d_out, int out_size)
{
    const float* x   = (const float*)d_in[0];
    const float* rel = (const float*)d_in[1];
    const float* Wq  = (const float*)d_in[2];
    const float* Wk  = (const float*)d_in[3];
    const float* Wv  = (const float*)d_in[4];
    const float* Wo  = (const float*)d_in[5];
    const float* bo  = (const float*)d_in[6];
    float* out = (float*)d_out;

    float *qb, *kb, *vb, *ctx;
    cudaGetSymbolAddress((void**)&qb,  g_q);
    cudaGetSymbolAddress((void**)&kb,  g_k);
    cudaGetSymbolAddress((void**)&vb,  g_v);
    cudaGetSymbolAddress((void**)&ctx, g_ctx);

    cudaFuncSetAttribute(attn_kernel,
                         cudaFuncAttributeMaxDynamicSharedMemorySize,
                         SM_ATTN_BYTES);

    const int M = BATCH * SEQ;  // 4096

    // fused q|k|v projections: x=0..7 -> q (permuted); x=8 -> k + v^T
    {
        dim3 grid(9, M / 128);
        gemm_tf32<4><<<grid, 256>>>(x, Wq, Wk, Wv, nullptr,
                                    qb, kb, vb, M, DM, DM);
    }
    // fused attention (fp16 MMA)
    attn_kernel<<<SEQ, 256, SM_ATTN_BYTES>>>(rel, qb, kb, vb, ctx);

    // out = ctx @ Wo^T + bo
    {
        dim3 grid(8, M / 128);
        gemm_tf32<2><<<grid, 256>>>(ctx, Wo, nullptr, nullptr, bo,
                                    out, nullptr, nullptr, M, DM, DM);
    }
}

// round 14
// speedup vs baseline: 2.6232x; 1.1370x over previous
#include <cuda_runtime.h>
#include <cuda_fp16.h>
#include <math.h>
#include <stdint.h>

#define BATCH 4
#define SEQ   1024
#define DM    1024
#define NH    16
#define DH    64

// Scratch (device globals — no allocation allowed)
__device__ float g_q[(size_t)BATCH*NH*SEQ*DH];   // [b*NH+h][s][d]
__device__ float g_k[(size_t)BATCH*SEQ*DH];      // [b*S+s][d]
__device__ float g_v[(size_t)BATCH*SEQ*DH];      // used as V^T: [d][b*S+j]
__device__ float g_ctx[(size_t)BATCH*SEQ*DM];    // [b*S+s][h*DH+d]

// ---------------------------------------------------------------------------
// helpers
// ---------------------------------------------------------------------------
__device__ __forceinline__ uint32_t f2h2(float a, float b) {
    __half2 h = __floats2half2_rn(a, b);
    return *(uint32_t*)&h;
}

__device__ __forceinline__ void mma_f16(float* c, const uint32_t* a, const uint32_t* b) {
    asm volatile(
        "mma.sync.aligned.m16n8k16.row.col.f32.f16.f16.f32 "
        "{%0,%1,%2,%3}, {%4,%5,%6,%7}, {%8,%9}, {%0,%1,%2,%3};\n"
        : "+f"(c[0]), "+f"(c[1]), "+f"(c[2]), "+f"(c[3])
        : "r"(a[0]), "r"(a[1]), "r"(a[2]), "r"(a[3]), "r"(b[0]), "r"(b[1]));
}

// ---------------------------------------------------------------------------
// FP16 GEMM (fp32 accum), double-buffered smem, 1 barrier per 16-k slab.
// MODE 2: out = A @ Wo^T + bias
// MODE 4: fused projections: x<8 -> q permuted; x==8 -> k + v-TRANSPOSED.
// smem rows: 8 half2 per 16-k slab, pitch 12 u32 (conflict-free frags).
// ---------------------------------------------------------------------------
#define GP2 12   // pitch in u32

template<int MODE>
__global__ __launch_bounds__(256, 2)
void gemm_f16(const float* __restrict__ A, const float* __restrict__ B,
              const float* __restrict__ Bk, const float* __restrict__ Bv,
              const float* __restrict__ bias,
              float* __restrict__ C, float* __restrict__ Ck, float* __restrict__ Cv,
              int M, int N, int K)
{
    __shared__ uint32_t sA[2][128 * GP2];
    __shared__ uint32_t sB[2][128 * GP2];

    const int tid  = threadIdx.x;
    const int lane = tid & 31;
    const int w    = tid >> 5;
    const int wr   = w >> 1;
    const int wc   = w & 1;
    const int g    = lane >> 2;
    const int t    = lane & 3;
    const int m0   = blockIdx.y * 128;
    const bool kv  = (MODE == 4) && (blockIdx.x == 8);
    const int n0   = kv ? 0 : blockIdx.x * 128;

    const int ldr = tid >> 2;        // 0..63
    const int ldc = (tid & 3) * 4;   // float offset in k-slab
    const int ldq = (tid & 3) * 2;   // half2 offset in smem row

    float acc[2][8][4];
    #pragma unroll
    for (int mt = 0; mt < 2; mt++)
        #pragma unroll
        for (int nt = 0; nt < 8; nt++)
            #pragma unroll
            for (int q = 0; q < 4; q++) acc[mt][nt][q] = 0.f;

    float4 ar[2], br[2];

    // prologue: slab 0 -> regs -> smem buf 0; slab 1 -> regs
    #pragma unroll
    for (int h = 0; h < 2; h++) {
        const int row = ldr + h * 64;
        ar[h] = *(const float4*)&A[(size_t)(m0 + row) * K + ldc];
        if (MODE == 4 && kv) {
            const float* Bs = (row >= 64) ? Bv : Bk;
            br[h] = *(const float4*)&Bs[(size_t)(row & 63) * K + ldc];
        } else {
            br[h] = *(const float4*)&B[(size_t)(n0 + row) * K + ldc];
        }
    }
    {
        #pragma unroll
        for (int h = 0; h < 2; h++) {
            const int row = ldr + h * 64;
            uint32_t* da = &sA[0][row * GP2 + ldq];
            da[0] = f2h2(ar[h].x, ar[h].y); da[1] = f2h2(ar[h].z, ar[h].w);
            uint32_t* db = &sB[0][row * GP2 + ldq];
            db[0] = f2h2(br[h].x, br[h].y); db[1] = f2h2(br[h].z, br[h].w);
        }
        #pragma unroll
        for (int h = 0; h < 2; h++) {
            const int row = ldr + h * 64;
            ar[h] = *(const float4*)&A[(size_t)(m0 + row) * K + 16 + ldc];
            if (MODE == 4 && kv) {
                const float* Bs = (row >= 64) ? Bv : Bk;
                br[h] = *(const float4*)&Bs[(size_t)(row & 63) * K + 16 + ldc];
            } else {
                br[h] = *(const float4*)&B[(size_t)(n0 + row) * K + 16 + ldc];
            }
        }
    }
    __syncthreads();

    const int nIt = K >> 4;
    for (int it = 0; it < nIt; it++) {
        const int buf = it & 1;
        const uint32_t* cA = sA[buf];
        const uint32_t* cB = sB[buf];

        // MMA over this slab: one K=16 chunk
        {
            uint32_t af[2][4], bf[8][2];
            #pragma unroll
            for (int mt = 0; mt < 2; mt++) {
                const int mr = wr * 32 + mt * 16;
                af[mt][0] = cA[(mr + g) * GP2 + t];
                af[mt][1] = cA[(mr + g + 8) * GP2 + t];
                af[mt][2] = cA[(mr + g) * GP2 + t + 4];
                af[mt][3] = cA[(mr + g + 8) * GP2 + t + 4];
            }
            #pragma unroll
            for (int nt = 0; nt < 8; nt++) {
                const int nn = wc * 64 + nt * 8 + g;
                bf[nt][0] = cB[nn * GP2 + t];
                bf[nt][1] = cB[nn * GP2 + t + 4];
            }
            #pragma unroll
            for (int mt = 0; mt < 2; mt++)
                #pragma unroll
                for (int nt = 0; nt < 8; nt++)
                    mma_f16(acc[mt][nt], af[mt], bf[nt]);
        }

        // stage next slab into the other buffer, prefetch slab after
        if (it + 1 < nIt) {
            uint32_t* dA = sA[buf ^ 1];
            uint32_t* dB = sB[buf ^ 1];
            #pragma unroll
            for (int h = 0; h < 2; h++) {
                const int row = ldr + h * 64;
                uint32_t* da = &dA[row * GP2 + ldq];
                da[0] = f2h2(ar[h].x, ar[h].y); da[1] = f2h2(ar[h].z, ar[h].w);
                uint32_t* db = &dB[row * GP2 + ldq];
                db[0] = f2h2(br[h].x, br[h].y); db[1] = f2h2(br[h].z, br[h].w);
            }
            if (it + 2 < nIt) {
                const int k0 = (it + 2) * 16;
                #pragma unroll
                for (int h = 0; h < 2; h++) {
                    const int row = ldr + h * 64;
                    ar[h] = *(const float4*)&A[(size_t)(m0 + row) * K + k0 + ldc];
                    if (MODE == 4 && kv) {
                        const float* Bs = (row >= 64) ? Bv : Bk;
                        br[h] = *(const float4*)&Bs[(size_t)(row & 63) * K + k0 + ldc];
                    } else {
                        br[h] = *(const float4*)&B[(size_t)(n0 + row) * K + k0 + ldc];
                    }
                }
            }
        }
        __syncthreads();
    }

    // epilogue
    #pragma unroll
    for (int mt = 0; mt < 2; mt++) {
        #pragma unroll
        for (int rr = 0; rr < 2; rr++) {
            const int m = m0 + wr * 32 + mt * 16 + g + rr * 8;
            #pragma unroll
            for (int nt = 0; nt < 8; nt++) {
                const int n = n0 + wc * 64 + nt * 8 + 2 * t;
                const float v0 = acc[mt][nt][rr * 2 + 0];
                const float v1 = acc[mt][nt][rr * 2 + 1];
                if (MODE == 2) {
                    *(float2*)&C[(size_t)m * N + n] =
                        make_float2(v0 + bias[n], v1 + bias[n + 1]);
                } else if (MODE == 4 && !kv) {
                    const int b = m >> 10, s = m & 1023;
                    const int h = n >> 6, d = n & 63;
                    *(float2*)&C[(((size_t)(b * NH + h)) * SEQ + s) * DH + d] =
                        make_float2(v0, v1);
                } else {
                    const int nn = nt * 8 + 2 * t;
                    if (!wc) {
                        // k: [m][64]
                        *(float2*)&Ck[(size_t)m * 64 + nn] = make_float2(v0, v1);
                    } else {
                        // v TRANSPOSED: [d][m] (m = b*S + j)
                        Cv[(size_t)nn * 4096 + m]       = v0;
                        Cv[(size_t)(nn + 1) * 4096 + m] = v1;
                    }
                }
            }
        }
    }
}

// ---------------------------------------------------------------------------
// Fused attention (R12, unchanged): FP16 MMA (m16n8k16), V pre-transposed.
// One CTA per query i; 8 warps = (batch, half); 2 CTAs/SM.
// ---------------------------------------------------------------------------
#define QP 36   // pitch in u32 (half2) units

#define SMU_Q   (64 * QP)
#define SMU_KV  (256 * QP)     // KR rows [b*64+j] / V^T rows [b*64+d], time-shared
#define SMU_P   (64 * QP)
#define SMU_TOT (SMU_Q + SMU_KV + SMU_P + 256)
#define SM_ATTN_BYTES (SMU_TOT * 4)

__global__ __launch_bounds__(256, 2)
void attn_kernel(const float* __restrict__ rel,
                 const float* __restrict__ qb,
                 const float* __restrict__ kb,
                 const float* __restrict__ vt,   // V^T [64][4096]
                 float* __restrict__ ctx)
{
    extern __shared__ uint32_t smu[];
    uint32_t* sQ   = smu;                    // [64][QP] half2 Q (pre-scaled)
    uint32_t* sKV  = sQ + SMU_Q;             // KR/V^T half2
    uint32_t* sP   = sKV + SMU_KV;           // [64][QP] half2 probs
    float*    sExM = (float*)(sP + SMU_P);   // [8 warps][16 rows]
    float*    sExS = sExM + 128;

    const int i    = blockIdx.x;
    const int tid  = threadIdx.x;
    const int lane = tid & 31;
    const int w    = tid >> 5;
    const int b    = w >> 1;           // batch
    const int half = w & 1;            // j-half (scores) / d-half (AV)
    const int g    = lane >> 2;
    const int t    = lane & 3;
    const unsigned FULL = 0xffffffffu;

    // Load Q (64 rows x 64 d) -> half2, pre-scaled by 1/8
    #pragma unroll
    for (int tix = 0; tix < 8; tix++) {
        const int idx = tix * 256 + tid;   // 2048 half2
        const int r  = idx >> 5;
        const int dq = idx & 31;
        const float2 q2 = *(const float2*)&qb[((size_t)r * SEQ + i) * DH + 2 * dq];
        sQ[r * QP + dq] = f2h2(0.125f * q2.x, 0.125f * q2.y);
    }

    // prologue: prefetch tile-0 rel into registers
    float4 relbuf[4];
    #pragma unroll
    for (int tix = 0; tix < 4; tix++) {
        const int idx = tix * 256 + tid;
        const int j  = idx >> 4;
        const int d4 = (idx & 15) * 4;
        relbuf[tix] = *(const float4*)&rel[((size_t)i * SEQ + j) * DH + d4];
    }

    // per-warp running softmax state for rows b*16+g, b*16+g+8
    float mr0 = -INFINITY, mr1 = -INFINITY, lr0 = 0.f, lr1 = 0.f;
    float cacc[4][4];
    #pragma unroll
    for (int nt = 0; nt < 4; nt++)
        #pragma unroll
        for (int q = 0; q < 4; q++) cacc[nt][q] = 0.f;

    for (int j0 = 0; j0 < SEQ; j0 += 64) {
        __syncthreads();   // S0: prev tile's AV reads of sKV/sP complete

        // ---- build KR[b][j][d] = half2(K + rel), rna ----
        #pragma unroll
        for (int tix = 0; tix < 4; tix++) {
            const int idx = tix * 256 + tid;
            const int j  = idx >> 4;
            const int d4 = (idx & 15) * 4;
            const int dq = d4 >> 1;
            const float4 rv = relbuf[tix];
            #pragma unroll
            for (int bb = 0; bb < 4; bb++) {
                const float4 k4 = *(const float4*)&kb[((size_t)(bb * SEQ) + j0 + j) * DH + d4];
                const uint32_t h0 = f2h2(k4.x + rv.x, k4.y + rv.y);
                const uint32_t h1 = f2h2(k4.z + rv.z, k4.w + rv.w);
                *(uint2*)&sKV[(bb * 64 + j) * QP + dq] = make_uint2(h0, h1);
            }
        }
        __syncthreads();   // S1

        // prefetch next tile's rel (hidden behind MMA)
        if (j0 + 64 < SEQ) {
            #pragma unroll
            for (int tix = 0; tix < 4; tix++) {
                const int idx = tix * 256 + tid;
                const int j  = idx >> 4;
                const int d4 = (idx & 15) * 4;
                relbuf[tix] =
                    *(const float4*)&rel[((size_t)i * SEQ + j0 + 64 + j) * DH + d4];
            }
        }

        // ---- scores MMA (f16 k16): rows b*16+{g,g+8}, cols half*32+nt*8+{2t,2t+1}
        float pr[4][4];
        #pragma unroll
        for (int nt = 0; nt < 4; nt++)
            #pragma unroll
            for (int q = 0; q < 4; q++) pr[nt][q] = 0.f;

        #pragma unroll
        for (int ks = 0; ks < 4; ks++) {
            const int kq = ks * 8;   // half2 index of k-chunk
            uint32_t af[4], bf[2];
            af[0] = sQ[(b * 16 + g) * QP + kq + t];
            af[1] = sQ[(b * 16 + g + 8) * QP + kq + t];
            af[2] = sQ[(b * 16 + g) * QP + kq + t + 4];
            af[3] = sQ[(b * 16 + g + 8) * QP + kq + t + 4];
            #pragma unroll
            for (int nt = 0; nt < 4; nt++) {
                const int n = half * 32 + nt * 8 + g;
                bf[0] = sKV[(b * 64 + n) * QP + kq + t];
                bf[1] = sKV[(b * 64 + n) * QP + kq + t + 4];
                mma_f16(pr[nt], af, bf);
            }
        }

        // ---- row max (quad reduce) + cross-half exchange ----
        float m0 = -INFINITY, m1 = -INFINITY;
        #pragma unroll
        for (int nt = 0; nt < 4; nt++) {
            m0 = fmaxf(m0, fmaxf(pr[nt][0], pr[nt][1]));
            m1 = fmaxf(m1, fmaxf(pr[nt][2], pr[nt][3]));
        }
        m0 = fmaxf(m0, __shfl_xor_sync(FULL, m0, 1));
        m0 = fmaxf(m0, __shfl_xor_sync(FULL, m0, 2));
        m1 = fmaxf(m1, __shfl_xor_sync(FULL, m1, 1));
        m1 = fmaxf(m1, __shfl_xor_sync(FULL, m1, 2));
        if (t == 0) {
            sExM[w * 16 + g]     = m0;
            sExM[w * 16 + 8 + g] = m1;
        }
        __syncthreads();   // S2: sExM ready; KR reads done -> V may overwrite

        const float pm0 = sExM[(w ^ 1) * 16 + g];
        const float pm1 = sExM[(w ^ 1) * 16 + 8 + g];
        const float mn0 = fmaxf(mr0, fmaxf(m0, pm0));
        const float mn1 = fmaxf(mr1, fmaxf(m1, pm1));
        const float corr0 = __expf(mr0 - mn0);
        const float corr1 = __expf(mr1 - mn1);
        mr0 = mn0; mr1 = mn1;

        // ---- exp in registers, single half2 P write, row sums ----
        float s0 = 0.f, s1 = 0.f;
        #pragma unroll
        for (int nt = 0; nt < 4; nt++) {
            float p0 = __expf(pr[nt][0] - mn0);
            float p1 = __expf(pr[nt][1] - mn0);
            float p2 = __expf(pr[nt][2] - mn1);
            float p3 = __expf(pr[nt][3] - mn1);
            s0 += p0 + p1; s1 += p2 + p3;
            const int jq = half * 16 + nt * 4 + t;   // half2 index of cols 2t,2t+1
            sP[(b * 16 + g) * QP + jq]     = f2h2(p0, p1);
            sP[(b * 16 + g + 8) * QP + jq] = f2h2(p2, p3);
        }
        s0 += __shfl_xor_sync(FULL, s0, 1);
        s0 += __shfl_xor_sync(FULL, s0, 2);
        s1 += __shfl_xor_sync(FULL, s1, 1);
        s1 += __shfl_xor_sync(FULL, s1, 2);
        if (t == 0) {
            sExS[w * 16 + g]     = s0;
            sExS[w * 16 + 8 + g] = s1;
        }

        // ---- V^T: gmem [d][b*S+j] -> sKV[b*64+d][jq] half2 (coalesced) ----
        #pragma unroll
        for (int tix = 0; tix < 4; tix++) {
            const int idx = tix * 256 + tid;
            const int d  = idx >> 4;
            const int j4 = (idx & 15) * 4;
            const int jq = j4 >> 1;
            #pragma unroll
            for (int bb = 0; bb < 4; bb++) {
                const float4 v4 =
                    *(const float4*)&vt[(size_t)d * 4096 + bb * 1024 + j0 + j4];
                *(uint2*)&sKV[(bb * 64 + d) * QP + jq] =
                    make_uint2(f2h2(v4.x, v4.y), f2h2(v4.z, v4.w));
            }
        }
        __syncthreads();   // S3: sP, sKV(V^T), sExS ready

        lr0 = lr0 * corr0 + s0 + sExS[(w ^ 1) * 16 + g];
        lr1 = lr1 * corr1 + s1 + sExS[(w ^ 1) * 16 + 8 + g];

        // ---- rescale ctx + AV MMA (f16 k16): N=32 d (half), K=64 j ----
        #pragma unroll
        for (int nt = 0; nt < 4; nt++) {
            cacc[nt][0] *= corr0; cacc[nt][1] *= corr0;
            cacc[nt][2] *= corr1; cacc[nt][3] *= corr1;
        }
        #pragma unroll
        for (int ks = 0; ks < 4; ks++) {
            const int kq = ks * 8;   // half2 index along j
            uint32_t af[4], bf[2];
            af[0] = sP[(b * 16 + g) * QP + kq + t];
            af[1] = sP[(b * 16 + g + 8) * QP + kq + t];
            af[2] = sP[(b * 16 + g) * QP + kq + t + 4];
            af[3] = sP[(b * 16 + g + 8) * QP + kq + t + 4];
            #pragma unroll
            for (int nt = 0; nt < 4; nt++) {
                const int n = half * 32 + nt * 8 + g;   // d column
                bf[0] = sKV[(b * 64 + n) * QP + kq + t];
                bf[1] = sKV[(b * 64 + n) * QP + kq + t + 4];
                mma_f16(cacc[nt], af, bf);
            }
        }
    }

    // ---- epilogue: normalize + write ctx [b][i][h*DH + d] ----
    {
        const float inv0 = 1.f / lr0;
        const float inv1 = 1.f / lr1;
        const size_t base = ((size_t)(b * SEQ) + i) * DM;
        #pragma unroll
        for (int nt = 0; nt < 4; nt++) {
            const int d = half * 32 + nt * 8 + 2 * t;
            *(float2*)&ctx[base + g * DH + d] =
                make_float2(cacc[nt][0] * inv0, cacc[nt][1] * inv0);
            *(float2*)&ctx[base + (g + 8) * DH + d] =
                make_float2(cacc[nt][2] * inv1, cacc[nt][3] * inv1);
        }
    }
}

// ---------------------------------------------------------------------------
extern "C" void kernel_launch(void* const* d_in, const int* in_sizes, int n_in,
                              void* d_out, int out_size)
{
    const float* x   = (const float*)d_in[0];
    const float* rel = (const float*)d_in[1];
    const float* Wq  = (const float*)d_in[2];
    const float* Wk  = (const float*)d_in[3];
    const float* Wv  = (const float*)d_in[4];
    const float* Wo  = (const float*)d_in[5];
    const float* bo  = (const float*)d_in[6];
    float* out = (float*)d_out;

    float *qb, *kb, *vb, *ctx;
    cudaGetSymbolAddress((void**)&qb,  g_q);
    cudaGetSymbolAddress((void**)&kb,  g_k);
    cudaGetSymbolAddress((void**)&vb,  g_v);
    cudaGetSymbolAddress((void**)&ctx, g_ctx);

    cudaFuncSetAttribute(attn_kernel,
                         cudaFuncAttributeMaxDynamicSharedMemorySize,
                         SM_ATTN_BYTES);

    const int M = BATCH * SEQ;  // 4096

    // fused q|k|v projections: x=0..7 -> q (permuted); x=8 -> k + v^T
    {
        dim3 grid(9, M / 128);
        gemm_f16<4><<<grid, 256>>>(x, Wq, Wk, Wv, nullptr,
                                   qb, kb, vb, M, DM, DM);
    }
    // fused attention (fp16 MMA)
    attn_kernel<<<SEQ, 256, SM_ATTN_BYTES>>>(rel, qb, kb, vb, ctx);

    // out = ctx @ Wo^T + bo
    {
        dim3 grid(8, M / 128);
        gemm_f16<2><<<grid, 256>>>(ctx, Wo, nullptr, nullptr, bo,
                                   out, nullptr, nullptr, M, DM, DM);
    }
}

// round 15
// speedup vs baseline: 2.8190x; 1.0747x over previous
#include <cuda_runtime.h>
#include <cuda_fp16.h>
#include <math.h>
#include <stdint.h>

#define BATCH 4
#define SEQ   1024
#define DM    1024
#define NH    16
#define DH    64

// Scratch (device globals — no allocation allowed)
__device__ float g_q[(size_t)BATCH*NH*SEQ*DH];   // [b*NH+h][s][d]
__device__ float g_k[(size_t)BATCH*SEQ*DH];      // [b*S+s][d]
__device__ float g_v[(size_t)BATCH*SEQ*DH];      // holds V^T as HALF: [d][b*S+j]
__device__ float g_ctx[(size_t)BATCH*SEQ*DM];    // [b*S+s][h*DH+d]

// ---------------------------------------------------------------------------
// helpers
// ---------------------------------------------------------------------------
__device__ __forceinline__ uint32_t f2h2(float a, float b) {
    __half2 h = __floats2half2_rn(a, b);
    return *(uint32_t*)&h;
}

__device__ __forceinline__ void mma_f16(float* c, const uint32_t* a, const uint32_t* b) {
    asm volatile(
        "mma.sync.aligned.m16n8k16.row.col.f32.f16.f16.f32 "
        "{%0,%1,%2,%3}, {%4,%5,%6,%7}, {%8,%9}, {%0,%1,%2,%3};\n"
        : "+f"(c[0]), "+f"(c[1]), "+f"(c[2]), "+f"(c[3])
        : "r"(a[0]), "r"(a[1]), "r"(a[2]), "r"(a[3]), "r"(b[0]), "r"(b[1]));
}

__device__ __forceinline__ void cp_async16(uint32_t smem_addr, const void* gptr) {
    asm volatile("cp.async.ca.shared.global [%0], [%1], 16;"
                 :: "r"(smem_addr), "l"(gptr));
}

// ---------------------------------------------------------------------------
// FP16 GEMM (fp32 accum), double-buffered smem (R13).
// MODE 2: out = A @ Wo^T + bias
// MODE 4: fused projections: x<8 -> q permuted; x==8 -> k + v^T-as-HALF.
// ---------------------------------------------------------------------------
#define GP2 12   // pitch in u32

template<int MODE>
__global__ __launch_bounds__(256, 2)
void gemm_f16(const float* __restrict__ A, const float* __restrict__ B,
              const float* __restrict__ Bk, const float* __restrict__ Bv,
              const float* __restrict__ bias,
              float* __restrict__ C, float* __restrict__ Ck, float* __restrict__ Cv,
              int M, int N, int K)
{
    __shared__ uint32_t sA[2][128 * GP2];
    __shared__ uint32_t sB[2][128 * GP2];

    const int tid  = threadIdx.x;
    const int lane = tid & 31;
    const int w    = tid >> 5;
    const int wr   = w >> 1;
    const int wc   = w & 1;
    const int g    = lane >> 2;
    const int t    = lane & 3;
    const int m0   = blockIdx.y * 128;
    const bool kv  = (MODE == 4) && (blockIdx.x == 8);
    const int n0   = kv ? 0 : blockIdx.x * 128;

    const int ldr = tid >> 2;
    const int ldc = (tid & 3) * 4;
    const int ldq = (tid & 3) * 2;

    float acc[2][8][4];
    #pragma unroll
    for (int mt = 0; mt < 2; mt++)
        #pragma unroll
        for (int nt = 0; nt < 8; nt++)
            #pragma unroll
            for (int q = 0; q < 4; q++) acc[mt][nt][q] = 0.f;

    float4 ar[2], br[2];

    #pragma unroll
    for (int h = 0; h < 2; h++) {
        const int row = ldr + h * 64;
        ar[h] = *(const float4*)&A[(size_t)(m0 + row) * K + ldc];
        if (MODE == 4 && kv) {
            const float* Bs = (row >= 64) ? Bv : Bk;
            br[h] = *(const float4*)&Bs[(size_t)(row & 63) * K + ldc];
        } else {
            br[h] = *(const float4*)&B[(size_t)(n0 + row) * K + ldc];
        }
    }
    {
        #pragma unroll
        for (int h = 0; h < 2; h++) {
            const int row = ldr + h * 64;
            uint32_t* da = &sA[0][row * GP2 + ldq];
            da[0] = f2h2(ar[h].x, ar[h].y); da[1] = f2h2(ar[h].z, ar[h].w);
            uint32_t* db = &sB[0][row * GP2 + ldq];
            db[0] = f2h2(br[h].x, br[h].y); db[1] = f2h2(br[h].z, br[h].w);
        }
        #pragma unroll
        for (int h = 0; h < 2; h++) {
            const int row = ldr + h * 64;
            ar[h] = *(const float4*)&A[(size_t)(m0 + row) * K + 16 + ldc];
            if (MODE == 4 && kv) {
                const float* Bs = (row >= 64) ? Bv : Bk;
                br[h] = *(const float4*)&Bs[(size_t)(row & 63) * K + 16 + ldc];
            } else {
                br[h] = *(const float4*)&B[(size_t)(n0 + row) * K + 16 + ldc];
            }
        }
    }
    __syncthreads();

    const int nIt = K >> 4;
    for (int it = 0; it < nIt; it++) {
        const int buf = it & 1;
        const uint32_t* cA = sA[buf];
        const uint32_t* cB = sB[buf];

        {
            uint32_t af[2][4], bf[8][2];
            #pragma unroll
            for (int mt = 0; mt < 2; mt++) {
                const int mr = wr * 32 + mt * 16;
                af[mt][0] = cA[(mr + g) * GP2 + t];
                af[mt][1] = cA[(mr + g + 8) * GP2 + t];
                af[mt][2] = cA[(mr + g) * GP2 + t + 4];
                af[mt][3] = cA[(mr + g + 8) * GP2 + t + 4];
            }
            #pragma unroll
            for (int nt = 0; nt < 8; nt++) {
                const int nn = wc * 64 + nt * 8 + g;
                bf[nt][0] = cB[nn * GP2 + t];
                bf[nt][1] = cB[nn * GP2 + t + 4];
            }
            #pragma unroll
            for (int mt = 0; mt < 2; mt++)
                #pragma unroll
                for (int nt = 0; nt < 8; nt++)
                    mma_f16(acc[mt][nt], af[mt], bf[nt]);
        }

        if (it + 1 < nIt) {
            uint32_t* dA = sA[buf ^ 1];
            uint32_t* dB = sB[buf ^ 1];
            #pragma unroll
            for (int h = 0; h < 2; h++) {
                const int row = ldr + h * 64;
                uint32_t* da = &dA[row * GP2 + ldq];
                da[0] = f2h2(ar[h].x, ar[h].y); da[1] = f2h2(ar[h].z, ar[h].w);
                uint32_t* db = &dB[row * GP2 + ldq];
                db[0] = f2h2(br[h].x, br[h].y); db[1] = f2h2(br[h].z, br[h].w);
            }
            if (it + 2 < nIt) {
                const int k0 = (it + 2) * 16;
                #pragma unroll
                for (int h = 0; h < 2; h++) {
                    const int row = ldr + h * 64;
                    ar[h] = *(const float4*)&A[(size_t)(m0 + row) * K + k0 + ldc];
                    if (MODE == 4 && kv) {
                        const float* Bs = (row >= 64) ? Bv : Bk;
                        br[h] = *(const float4*)&Bs[(size_t)(row & 63) * K + k0 + ldc];
                    } else {
                        br[h] = *(const float4*)&B[(size_t)(n0 + row) * K + k0 + ldc];
                    }
                }
            }
        }
        __syncthreads();
    }

    #pragma unroll
    for (int mt = 0; mt < 2; mt++) {
        #pragma unroll
        for (int rr = 0; rr < 2; rr++) {
            const int m = m0 + wr * 32 + mt * 16 + g + rr * 8;
            #pragma unroll
            for (int nt = 0; nt < 8; nt++) {
                const int n = n0 + wc * 64 + nt * 8 + 2 * t;
                const float v0 = acc[mt][nt][rr * 2 + 0];
                const float v1 = acc[mt][nt][rr * 2 + 1];
                if (MODE == 2) {
                    *(float2*)&C[(size_t)m * N + n] =
                        make_float2(v0 + bias[n], v1 + bias[n + 1]);
                } else if (MODE == 4 && !kv) {
                    const int b = m >> 10, s = m & 1023;
                    const int h = n >> 6, d = n & 63;
                    *(float2*)&C[(((size_t)(b * NH + h)) * SEQ + s) * DH + d] =
                        make_float2(v0, v1);
                } else {
                    const int nn = nt * 8 + 2 * t;
                    if (!wc) {
                        *(float2*)&Ck[(size_t)m * 64 + nn] = make_float2(v0, v1);
                    } else {
                        // v^T as HALF: [d][m] (m = b*S + j)
                        __half* vh = (__half*)Cv;
                        vh[(size_t)nn * 4096 + m]       = __float2half_rn(v0);
                        vh[(size_t)(nn + 1) * 4096 + m] = __float2half_rn(v1);
                    }
                }
            }
        }
    }
}

// ---------------------------------------------------------------------------
// Fused attention v5: fp16 MMA; V^T (half) copied via cp.async at tile-top
// into a DEDICATED sV buffer, overlapping KR build + scores + softmax.
// One CTA per query i; 8 warps = (batch, half); 2 CTAs/SM.
// ---------------------------------------------------------------------------
#define QP 36   // pitch in u32 (half2) units

#define SMU_Q   (64 * QP)
#define SMU_KR  (256 * QP)     // KR rows [b*64+j]
#define SMU_V   (256 * QP)     // V^T rows [b*64+d]
#define SMU_P   (64 * QP)
#define SMU_TOT (SMU_Q + SMU_KR + SMU_V + SMU_P + 256)
#define SM_ATTN_BYTES (SMU_TOT * 4)

__global__ __launch_bounds__(256, 2)
void attn_kernel(const float* __restrict__ rel,
                 const float* __restrict__ qb,
                 const float* __restrict__ kb,
                 const float* __restrict__ vtf,  // V^T half [64][4096]
                 float* __restrict__ ctx)
{
    extern __shared__ uint32_t smu[];
    uint32_t* sQ   = smu;                    // [64][QP] half2 Q (pre-scaled)
    uint32_t* sKR  = sQ + SMU_Q;             // KR half2
    uint32_t* sV   = sKR + SMU_KR;           // V^T half2
    uint32_t* sP   = sV + SMU_V;             // [64][QP] half2 probs
    float*    sExM = (float*)(sP + SMU_P);   // [8 warps][16 rows]
    float*    sExS = sExM + 128;

    const __half* vt = (const __half*)vtf;

    const int i    = blockIdx.x;
    const int tid  = threadIdx.x;
    const int lane = tid & 31;
    const int w    = tid >> 5;
    const int b    = w >> 1;           // batch
    const int half = w & 1;            // j-half (scores) / d-half (AV)
    const int g    = lane >> 2;
    const int t    = lane & 3;
    const unsigned FULL = 0xffffffffu;

    const uint32_t sV_base = (uint32_t)__cvta_generic_to_shared(sV);

    // Load Q (64 rows x 64 d) -> half2, pre-scaled by 1/8
    #pragma unroll
    for (int tix = 0; tix < 8; tix++) {
        const int idx = tix * 256 + tid;
        const int r  = idx >> 5;
        const int dq = idx & 31;
        const float2 q2 = *(const float2*)&qb[((size_t)r * SEQ + i) * DH + 2 * dq];
        sQ[r * QP + dq] = f2h2(0.125f * q2.x, 0.125f * q2.y);
    }

    // prologue: prefetch tile-0 rel into registers
    float4 relbuf[4];
    #pragma unroll
    for (int tix = 0; tix < 4; tix++) {
        const int idx = tix * 256 + tid;
        const int j  = idx >> 4;
        const int d4 = (idx & 15) * 4;
        relbuf[tix] = *(const float4*)&rel[((size_t)i * SEQ + j) * DH + d4];
    }

    // per-warp running softmax state for rows b*16+g, b*16+g+8
    float mr0 = -INFINITY, mr1 = -INFINITY, lr0 = 0.f, lr1 = 0.f;
    float cacc[4][4];
    #pragma unroll
    for (int nt = 0; nt < 4; nt++)
        #pragma unroll
        for (int q = 0; q < 4; q++) cacc[nt][q] = 0.f;

    for (int j0 = 0; j0 < SEQ; j0 += 64) {
        __syncthreads();   // S0: prev tile's AV reads of sV/sP done

        // ---- V^T half: issue cp.async NOW (consumed after S3) ----
        // 2048 16B-chunks: row = b*64+d (256), 8 chunks of 8 halves along j
        #pragma unroll
        for (int tix = 0; tix < 8; tix++) {
            const int idx = tix * 256 + tid;
            const int row = idx >> 3;            // bb*64 + d
            const int c8  = idx & 7;             // 8-half chunk along j
            const int bb  = row >> 6;
            const int d   = row & 63;
            cp_async16(sV_base + (row * QP + c8 * 4) * 4,
                       &vt[(size_t)d * 4096 + bb * 1024 + j0 + c8 * 8]);
        }
        asm volatile("cp.async.commit_group;");

        // ---- build KR[b][j][d] = half2(K + rel), rna ----
        #pragma unroll
        for (int tix = 0; tix < 4; tix++) {
            const int idx = tix * 256 + tid;
            const int j  = idx >> 4;
            const int d4 = (idx & 15) * 4;
            const int dq = d4 >> 1;
            const float4 rv = relbuf[tix];
            #pragma unroll
            for (int bb = 0; bb < 4; bb++) {
                const float4 k4 = *(const float4*)&kb[((size_t)(bb * SEQ) + j0 + j) * DH + d4];
                const uint32_t h0 = f2h2(k4.x + rv.x, k4.y + rv.y);
                const uint32_t h1 = f2h2(k4.z + rv.z, k4.w + rv.w);
                *(uint2*)&sKR[(bb * 64 + j) * QP + dq] = make_uint2(h0, h1);
            }
        }
        __syncthreads();   // S1: KR ready

        // prefetch next tile's rel (hidden behind MMA)
        if (j0 + 64 < SEQ) {
            #pragma unroll
            for (int tix = 0; tix < 4; tix++) {
                const int idx = tix * 256 + tid;
                const int j  = idx >> 4;
                const int d4 = (idx & 15) * 4;
                relbuf[tix] =
                    *(const float4*)&rel[((size_t)i * SEQ + j0 + 64 + j) * DH + d4];
            }
        }

        // ---- scores MMA (f16 k16) ----
        float pr[4][4];
        #pragma unroll
        for (int nt = 0; nt < 4; nt++)
            #pragma unroll
            for (int q = 0; q < 4; q++) pr[nt][q] = 0.f;

        #pragma unroll
        for (int ks = 0; ks < 4; ks++) {
            const int kq = ks * 8;
            uint32_t af[4], bf[2];
            af[0] = sQ[(b * 16 + g) * QP + kq + t];
            af[1] = sQ[(b * 16 + g + 8) * QP + kq + t];
            af[2] = sQ[(b * 16 + g) * QP + kq + t + 4];
            af[3] = sQ[(b * 16 + g + 8) * QP + kq + t + 4];
            #pragma unroll
            for (int nt = 0; nt < 4; nt++) {
                const int n = half * 32 + nt * 8 + g;
                bf[0] = sKR[(b * 64 + n) * QP + kq + t];
                bf[1] = sKR[(b * 64 + n) * QP + kq + t + 4];
                mma_f16(pr[nt], af, bf);
            }
        }

        // ---- row max (quad reduce) + cross-half exchange ----
        float m0 = -INFINITY, m1 = -INFINITY;
        #pragma unroll
        for (int nt = 0; nt < 4; nt++) {
            m0 = fmaxf(m0, fmaxf(pr[nt][0], pr[nt][1]));
            m1 = fmaxf(m1, fmaxf(pr[nt][2], pr[nt][3]));
        }
        m0 = fmaxf(m0, __shfl_xor_sync(FULL, m0, 1));
        m0 = fmaxf(m0, __shfl_xor_sync(FULL, m0, 2));
        m1 = fmaxf(m1, __shfl_xor_sync(FULL, m1, 1));
        m1 = fmaxf(m1, __shfl_xor_sync(FULL, m1, 2));
        if (t == 0) {
            sExM[w * 16 + g]     = m0;
            sExM[w * 16 + 8 + g] = m1;
        }
        __syncthreads();   // S2: sExM visible

        const float pm0 = sExM[(w ^ 1) * 16 + g];
        const float pm1 = sExM[(w ^ 1) * 16 + 8 + g];
        const float mn0 = fmaxf(mr0, fmaxf(m0, pm0));
        const float mn1 = fmaxf(mr1, fmaxf(m1, pm1));
        const float corr0 = __expf(mr0 - mn0);
        const float corr1 = __expf(mr1 - mn1);
        mr0 = mn0; mr1 = mn1;

        // ---- exp in registers, single half2 P write, row sums ----
        float s0 = 0.f, s1 = 0.f;
        #pragma unroll
        for (int nt = 0; nt < 4; nt++) {
            float p0 = __expf(pr[nt][0] - mn0);
            float p1 = __expf(pr[nt][1] - mn0);
            float p2 = __expf(pr[nt][2] - mn1);
            float p3 = __expf(pr[nt][3] - mn1);
            s0 += p0 + p1; s1 += p2 + p3;
            const int jq = half * 16 + nt * 4 + t;
            sP[(b * 16 + g) * QP + jq]     = f2h2(p0, p1);
            sP[(b * 16 + g + 8) * QP + jq] = f2h2(p2, p3);
        }
        s0 += __shfl_xor_sync(FULL, s0, 1);
        s0 += __shfl_xor_sync(FULL, s0, 2);
        s1 += __shfl_xor_sync(FULL, s1, 1);
        s1 += __shfl_xor_sync(FULL, s1, 2);
        if (t == 0) {
            sExS[w * 16 + g]     = s0;
            sExS[w * 16 + 8 + g] = s1;
        }

        asm volatile("cp.async.wait_group 0;" ::: "memory");
        __syncthreads();   // S3: sP, sV, sExS ready

        lr0 = lr0 * corr0 + s0 + sExS[(w ^ 1) * 16 + g];
        lr1 = lr1 * corr1 + s1 + sExS[(w ^ 1) * 16 + 8 + g];

        // ---- rescale ctx + AV MMA (f16 k16): N=32 d (half), K=64 j ----
        #pragma unroll
        for (int nt = 0; nt < 4; nt++) {
            cacc[nt][0] *= corr0; cacc[nt][1] *= corr0;
            cacc[nt][2] *= corr1; cacc[nt][3] *= corr1;
        }
        #pragma unroll
        for (int ks = 0; ks < 4; ks++) {
            const int kq = ks * 8;
            uint32_t af[4], bf[2];
            af[0] = sP[(b * 16 + g) * QP + kq + t];
            af[1] = sP[(b * 16 + g + 8) * QP + kq + t];
            af[2] = sP[(b * 16 + g) * QP + kq + t + 4];
            af[3] = sP[(b * 16 + g + 8) * QP + kq + t + 4];
            #pragma unroll
            for (int nt = 0; nt < 4; nt++) {
                const int n = half * 32 + nt * 8 + g;
                bf[0] = sV[(b * 64 + n) * QP + kq + t];
                bf[1] = sV[(b * 64 + n) * QP + kq + t + 4];
                mma_f16(cacc[nt], af, bf);
            }
        }
    }

    // ---- epilogue: normalize + write ctx [b][i][h*DH + d] ----
    {
        const float inv0 = 1.f / lr0;
        const float inv1 = 1.f / lr1;
        const size_t base = ((size_t)(b * SEQ) + i) * DM;
        #pragma unroll
        for (int nt = 0; nt < 4; nt++) {
            const int d = half * 32 + nt * 8 + 2 * t;
            *(float2*)&ctx[base + g * DH + d] =
                make_float2(cacc[nt][0] * inv0, cacc[nt][1] * inv0);
            *(float2*)&ctx[base + (g + 8) * DH + d] =
                make_float2(cacc[nt][2] * inv1, cacc[nt][3] * inv1);
        }
    }
}

// ---------------------------------------------------------------------------
extern "C" void kernel_launch(void* const* d_in, const int* in_sizes, int n_in,
                              void* d_out, int out_size)
{
    const float* x   = (const float*)d_in[0];
    const float* rel = (const float*)d_in[1];
    const float* Wq  = (const float*)d_in[2];
    const float* Wk  = (const float*)d_in[3];
    const float* Wv  = (const float*)d_in[4];
    const float* Wo  = (const float*)d_in[5];
    const float* bo  = (const float*)d_in[6];
    float* out = (float*)d_out;

    float *qb, *kb, *vb, *ctx;
    cudaGetSymbolAddress((void**)&qb,  g_q);
    cudaGetSymbolAddress((void**)&kb,  g_k);
    cudaGetSymbolAddress((void**)&vb,  g_v);
    cudaGetSymbolAddress((void**)&ctx, g_ctx);

    cudaFuncSetAttribute(attn_kernel,
                         cudaFuncAttributeMaxDynamicSharedMemorySize,
                         SM_ATTN_BYTES);

    const int M = BATCH * SEQ;  // 4096

    // fused q|k|v projections: x=0..7 -> q (permuted); x=8 -> k + v^T(half)
    {
        dim3 grid(9, M / 128);
        gemm_f16<4><<<grid, 256>>>(x, Wq, Wk, Wv, nullptr,
                                   qb, kb, vb, M, DM, DM);
    }
    // fused attention (fp16 MMA, cp.async V)
    attn_kernel<<<SEQ, 256, SM_ATTN_BYTES>>>(rel, qb, kb, vb, ctx);

    // out = ctx @ Wo^T + bo
    {
        dim3 grid(8, M / 128);
        gemm_f16<2><<<grid, 256>>>(ctx, Wo, nullptr, nullptr, bo,
                                   out, nullptr, nullptr, M, DM, DM);
    }
}

// round 16
// speedup vs baseline: 3.0561x; 1.0841x over previous
#include <cuda_runtime.h>
#include <cuda_fp16.h>
#include <math.h>
#include <stdint.h>

#define BATCH 4
#define SEQ   1024
#define DM    1024
#define NH    16
#define DH    64

// Scratch (device globals — no allocation allowed)
__device__ float g_q[(size_t)BATCH*NH*SEQ*DH];   // holds q as HALF: [b*NH+h][s][d]
__device__ float g_k[(size_t)BATCH*SEQ*DH];      // holds k as HALF: [b*S+s][d]
__device__ float g_v[(size_t)BATCH*SEQ*DH];      // holds V^T as HALF: [d][b*S+j]
__device__ float g_ctx[(size_t)BATCH*SEQ*DM];    // holds ctx as HALF: [b*S+s][h*DH+d]

// ---------------------------------------------------------------------------
// helpers
// ---------------------------------------------------------------------------
__device__ __forceinline__ uint32_t f2h2(float a, float b) {
    __half2 h = __floats2half2_rn(a, b);
    return *(uint32_t*)&h;
}

__device__ __forceinline__ uint32_t hadd2u(uint32_t a, uint32_t b) {
    __half2 r = __hadd2(*(__half2*)&a, *(__half2*)&b);
    return *(uint32_t*)&r;
}

__device__ __forceinline__ uint32_t hmul2u(uint32_t a, uint32_t b) {
    __half2 r = __hmul2(*(__half2*)&a, *(__half2*)&b);
    return *(uint32_t*)&r;
}

__device__ __forceinline__ void mma_f16(float* c, const uint32_t* a, const uint32_t* b) {
    asm volatile(
        "mma.sync.aligned.m16n8k16.row.col.f32.f16.f16.f32 "
        "{%0,%1,%2,%3}, {%4,%5,%6,%7}, {%8,%9}, {%0,%1,%2,%3};\n"
        : "+f"(c[0]), "+f"(c[1]), "+f"(c[2]), "+f"(c[3])
        : "r"(a[0]), "r"(a[1]), "r"(a[2]), "r"(a[3]), "r"(b[0]), "r"(b[1]));
}

__device__ __forceinline__ void cp_async16(uint32_t smem_addr, const void* gptr) {
    asm volatile("cp.async.ca.shared.global [%0], [%1], 16;"
                 :: "r"(smem_addr), "l"(gptr));
}

// ---------------------------------------------------------------------------
// FP16 GEMM (fp32 accum), double-buffered smem.
// MODE 2: out = ctx(HALF) @ Wo^T + bias   (A operand is half in gmem)
// MODE 4: fused projections (A=x fp32): x<8 -> q(HALF, permuted);
//         x==8 -> k(HALF) + v^T(HALF).
// ---------------------------------------------------------------------------
#define GP2 12   // pitch in u32

template<int MODE>
__global__ __launch_bounds__(256, 2)
void gemm_f16(const void* __restrict__ Araw, const float* __restrict__ B,
              const float* __restrict__ Bk, const float* __restrict__ Bv,
              const float* __restrict__ bias,
              float* __restrict__ C, float* __restrict__ Ck, float* __restrict__ Cv,
              int M, int N, int K)
{
    __shared__ uint32_t sA[2][128 * GP2];
    __shared__ uint32_t sB[2][128 * GP2];

    const float*  Af = (const float*)Araw;   // MODE 4
    const __half* Ah = (const __half*)Araw;  // MODE 2

    const int tid  = threadIdx.x;
    const int lane = tid & 31;
    const int w    = tid >> 5;
    const int wr   = w >> 1;
    const int wc   = w & 1;
    const int g    = lane >> 2;
    const int t    = lane & 3;
    const int m0   = blockIdx.y * 128;
    const bool kv  = (MODE == 4) && (blockIdx.x == 8);
    const int n0   = kv ? 0 : blockIdx.x * 128;

    const int ldr = tid >> 2;
    const int ldc = (tid & 3) * 4;   // element offset in k-slab (float or half)
    const int ldq = (tid & 3) * 2;   // u32 offset in smem row

    float acc[2][8][4];
    #pragma unroll
    for (int mt = 0; mt < 2; mt++)
        #pragma unroll
        for (int nt = 0; nt < 8; nt++)
            #pragma unroll
            for (int q = 0; q < 4; q++) acc[mt][nt][q] = 0.f;

    float4 ar[2], br[2];
    uint2  ar2[2];

    // prologue: slab 0 -> regs -> smem buf 0; slab 1 -> regs
    #pragma unroll
    for (int h = 0; h < 2; h++) {
        const int row = ldr + h * 64;
        if (MODE == 2) {
            ar2[h] = *(const uint2*)&Ah[(size_t)(m0 + row) * K + ldc];
        } else {
            ar[h] = *(const float4*)&Af[(size_t)(m0 + row) * K + ldc];
        }
        if (MODE == 4 && kv) {
            const float* Bs = (row >= 64) ? Bv : Bk;
            br[h] = *(const float4*)&Bs[(size_t)(row & 63) * K + ldc];
        } else {
            br[h] = *(const float4*)&B[(size_t)(n0 + row) * K + ldc];
        }
    }
    {
        #pragma unroll
        for (int h = 0; h < 2; h++) {
            const int row = ldr + h * 64;
            uint32_t* da = &sA[0][row * GP2 + ldq];
            if (MODE == 2) {
                da[0] = ar2[h].x; da[1] = ar2[h].y;
            } else {
                da[0] = f2h2(ar[h].x, ar[h].y); da[1] = f2h2(ar[h].z, ar[h].w);
            }
            uint32_t* db = &sB[0][row * GP2 + ldq];
            db[0] = f2h2(br[h].x, br[h].y); db[1] = f2h2(br[h].z, br[h].w);
        }
        #pragma unroll
        for (int h = 0; h < 2; h++) {
            const int row = ldr + h * 64;
            if (MODE == 2) {
                ar2[h] = *(const uint2*)&Ah[(size_t)(m0 + row) * K + 16 + ldc];
            } else {
                ar[h] = *(const float4*)&Af[(size_t)(m0 + row) * K + 16 + ldc];
            }
            if (MODE == 4 && kv) {
                const float* Bs = (row >= 64) ? Bv : Bk;
                br[h] = *(const float4*)&Bs[(size_t)(row & 63) * K + 16 + ldc];
            } else {
                br[h] = *(const float4*)&B[(size_t)(n0 + row) * K + 16 + ldc];
            }
        }
    }
    __syncthreads();

    const int nIt = K >> 4;
    for (int it = 0; it < nIt; it++) {
        const int buf = it & 1;
        const uint32_t* cA = sA[buf];
        const uint32_t* cB = sB[buf];

        {
            uint32_t af[2][4], bf[8][2];
            #pragma unroll
            for (int mt = 0; mt < 2; mt++) {
                const int mr = wr * 32 + mt * 16;
                af[mt][0] = cA[(mr + g) * GP2 + t];
                af[mt][1] = cA[(mr + g + 8) * GP2 + t];
                af[mt][2] = cA[(mr + g) * GP2 + t + 4];
                af[mt][3] = cA[(mr + g + 8) * GP2 + t + 4];
            }
            #pragma unroll
            for (int nt = 0; nt < 8; nt++) {
                const int nn = wc * 64 + nt * 8 + g;
                bf[nt][0] = cB[nn * GP2 + t];
                bf[nt][1] = cB[nn * GP2 + t + 4];
            }
            #pragma unroll
            for (int mt = 0; mt < 2; mt++)
                #pragma unroll
                for (int nt = 0; nt < 8; nt++)
                    mma_f16(acc[mt][nt], af[mt], bf[nt]);
        }

        if (it + 1 < nIt) {
            uint32_t* dA = sA[buf ^ 1];
            uint32_t* dB = sB[buf ^ 1];
            #pragma unroll
            for (int h = 0; h < 2; h++) {
                const int row = ldr + h * 64;
                uint32_t* da = &dA[row * GP2 + ldq];
                if (MODE == 2) {
                    da[0] = ar2[h].x; da[1] = ar2[h].y;
                } else {
                    da[0] = f2h2(ar[h].x, ar[h].y); da[1] = f2h2(ar[h].z, ar[h].w);
                }
                uint32_t* db = &dB[row * GP2 + ldq];
                db[0] = f2h2(br[h].x, br[h].y); db[1] = f2h2(br[h].z, br[h].w);
            }
            if (it + 2 < nIt) {
                const int k0 = (it + 2) * 16;
                #pragma unroll
                for (int h = 0; h < 2; h++) {
                    const int row = ldr + h * 64;
                    if (MODE == 2) {
                        ar2[h] = *(const uint2*)&Ah[(size_t)(m0 + row) * K + k0 + ldc];
                    } else {
                        ar[h] = *(const float4*)&Af[(size_t)(m0 + row) * K + k0 + ldc];
                    }
                    if (MODE == 4 && kv) {
                        const float* Bs = (row >= 64) ? Bv : Bk;
                        br[h] = *(const float4*)&Bs[(size_t)(row & 63) * K + k0 + ldc];
                    } else {
                        br[h] = *(const float4*)&B[(size_t)(n0 + row) * K + k0 + ldc];
                    }
                }
            }
        }
        __syncthreads();
    }

    // epilogue
    #pragma unroll
    for (int mt = 0; mt < 2; mt++) {
        #pragma unroll
        for (int rr = 0; rr < 2; rr++) {
            const int m = m0 + wr * 32 + mt * 16 + g + rr * 8;
            #pragma unroll
            for (int nt = 0; nt < 8; nt++) {
                const int n = n0 + wc * 64 + nt * 8 + 2 * t;
                const float v0 = acc[mt][nt][rr * 2 + 0];
                const float v1 = acc[mt][nt][rr * 2 + 1];
                if (MODE == 2) {
                    *(float2*)&C[(size_t)m * N + n] =
                        make_float2(v0 + bias[n], v1 + bias[n + 1]);
                } else if (MODE == 4 && !kv) {
                    // q as HALF, permuted [b,h,s,d]
                    const int b = m >> 10, s = m & 1023;
                    const int h = n >> 6, d = n & 63;
                    __half* qh = (__half*)C;
                    *(uint32_t*)&qh[(((size_t)(b * NH + h)) * SEQ + s) * DH + d] =
                        f2h2(v0, v1);
                } else {
                    const int nn = nt * 8 + 2 * t;
                    if (!wc) {
                        // k as HALF: [m][64]
                        __half* kh = (__half*)Ck;
                        *(uint32_t*)&kh[(size_t)m * 64 + nn] = f2h2(v0, v1);
                    } else {
                        // v^T as HALF: [d][m]
                        __half* vh = (__half*)Cv;
                        vh[(size_t)nn * 4096 + m]       = __float2half_rn(v0);
                        vh[(size_t)(nn + 1) * 4096 + m] = __float2half_rn(v1);
                    }
                }
            }
        }
    }
}

// ---------------------------------------------------------------------------
// Fused attention v6: all operands half in gmem. KR build = HADD2.
// V^T via cp.async at tile-top into dedicated sV. ctx written as half.
// One CTA per query i; 8 warps = (batch, half); 2 CTAs/SM.
// ---------------------------------------------------------------------------
#define QP 36   // pitch in u32 (half2) units

#define SMU_Q   (64 * QP)
#define SMU_KR  (256 * QP)
#define SMU_V   (256 * QP)
#define SMU_P   (64 * QP)
#define SMU_TOT (SMU_Q + SMU_KR + SMU_V + SMU_P + 256)
#define SM_ATTN_BYTES (SMU_TOT * 4)

__global__ __launch_bounds__(256, 2)
void attn_kernel(const float* __restrict__ rel,
                 const float* __restrict__ qbf,  // q half [64][S][64]
                 const float* __restrict__ kbf,  // k half [b*S][64]
                 const float* __restrict__ vtf,  // V^T half [64][4096]
                 float* __restrict__ ctxf)       // ctx half out
{
    extern __shared__ uint32_t smu[];
    uint32_t* sQ   = smu;
    uint32_t* sKR  = sQ + SMU_Q;
    uint32_t* sV   = sKR + SMU_KR;
    uint32_t* sP   = sV + SMU_V;
    float*    sExM = (float*)(sP + SMU_P);
    float*    sExS = sExM + 128;

    const __half* qh = (const __half*)qbf;
    const __half* kh = (const __half*)kbf;
    const __half* vt = (const __half*)vtf;
    __half*       ch = (__half*)ctxf;

    const int i    = blockIdx.x;
    const int tid  = threadIdx.x;
    const int lane = tid & 31;
    const int w    = tid >> 5;
    const int b    = w >> 1;
    const int half = w & 1;
    const int g    = lane >> 2;
    const int t    = lane & 3;
    const unsigned FULL = 0xffffffffu;

    const uint32_t sV_base = (uint32_t)__cvta_generic_to_shared(sV);

    // Load Q (64 rows x 64 d, half) -> sQ, scaled by 1/8 (exact in fp16)
    {
        const uint32_t eighth = f2h2(0.125f, 0.125f);
        #pragma unroll
        for (int tix = 0; tix < 4; tix++) {
            const int idx = tix * 256 + tid;
            const int r  = idx >> 4;
            const int c4 = idx & 15;           // quad of halves
            const uint2 v = *(const uint2*)&qh[((size_t)r * SEQ + i) * DH + c4 * 4];
            *(uint2*)&sQ[r * QP + c4 * 2] =
                make_uint2(hmul2u(v.x, eighth), hmul2u(v.y, eighth));
        }
    }

    // prologue: prefetch tile-0 rel into registers
    float4 relbuf[4];
    #pragma unroll
    for (int tix = 0; tix < 4; tix++) {
        const int idx = tix * 256 + tid;
        const int j  = idx >> 4;
        const int d4 = (idx & 15) * 4;
        relbuf[tix] = *(const float4*)&rel[((size_t)i * SEQ + j) * DH + d4];
    }

    float mr0 = -INFINITY, mr1 = -INFINITY, lr0 = 0.f, lr1 = 0.f;
    float cacc[4][4];
    #pragma unroll
    for (int nt = 0; nt < 4; nt++)
        #pragma unroll
        for (int q = 0; q < 4; q++) cacc[nt][q] = 0.f;

    for (int j0 = 0; j0 < SEQ; j0 += 64) {
        __syncthreads();   // S0

        // ---- V^T half: cp.async now (consumed after S3) ----
        #pragma unroll
        for (int tix = 0; tix < 8; tix++) {
            const int idx = tix * 256 + tid;
            const int row = idx >> 3;
            const int c8  = idx & 7;
            const int bb  = row >> 6;
            const int d   = row & 63;
            cp_async16(sV_base + (row * QP + c8 * 4) * 4,
                       &vt[(size_t)d * 4096 + bb * 1024 + j0 + c8 * 8]);
        }
        asm volatile("cp.async.commit_group;");

        // ---- build KR[b][j][d] = HADD2(K_h, rel_h) ----
        #pragma unroll
        for (int tix = 0; tix < 4; tix++) {
            const int idx = tix * 256 + tid;
            const int j  = idx >> 4;
            const int c4 = idx & 15;
            const int d4 = c4 * 4;
            const float4 rv = relbuf[tix];
            const uint32_t r0 = f2h2(rv.x, rv.y);
            const uint32_t r1 = f2h2(rv.z, rv.w);
            #pragma unroll
            for (int bb = 0; bb < 4; bb++) {
                const uint2 k2 = *(const uint2*)&kh[((size_t)(bb * SEQ) + j0 + j) * DH + d4];
                *(uint2*)&sKR[(bb * 64 + j) * QP + c4 * 2] =
                    make_uint2(hadd2u(k2.x, r0), hadd2u(k2.y, r1));
            }
        }
        __syncthreads();   // S1

        // prefetch next tile's rel
        if (j0 + 64 < SEQ) {
            #pragma unroll
            for (int tix = 0; tix < 4; tix++) {
                const int idx = tix * 256 + tid;
                const int j  = idx >> 4;
                const int d4 = (idx & 15) * 4;
                relbuf[tix] =
                    *(const float4*)&rel[((size_t)i * SEQ + j0 + 64 + j) * DH + d4];
            }
        }

        // ---- scores MMA (f16 k16) ----
        float pr[4][4];
        #pragma unroll
        for (int nt = 0; nt < 4; nt++)
            #pragma unroll
            for (int q = 0; q < 4; q++) pr[nt][q] = 0.f;

        #pragma unroll
        for (int ks = 0; ks < 4; ks++) {
            const int kq = ks * 8;
            uint32_t af[4], bf[2];
            af[0] = sQ[(b * 16 + g) * QP + kq + t];
            af[1] = sQ[(b * 16 + g + 8) * QP + kq + t];
            af[2] = sQ[(b * 16 + g) * QP + kq + t + 4];
            af[3] = sQ[(b * 16 + g + 8) * QP + kq + t + 4];
            #pragma unroll
            for (int nt = 0; nt < 4; nt++) {
                const int n = half * 32 + nt * 8 + g;
                bf[0] = sKR[(b * 64 + n) * QP + kq + t];
                bf[1] = sKR[(b * 64 + n) * QP + kq + t + 4];
                mma_f16(pr[nt], af, bf);
            }
        }

        // ---- row max + cross-half exchange ----
        float m0 = -INFINITY, m1 = -INFINITY;
        #pragma unroll
        for (int nt = 0; nt < 4; nt++) {
            m0 = fmaxf(m0, fmaxf(pr[nt][0], pr[nt][1]));
            m1 = fmaxf(m1, fmaxf(pr[nt][2], pr[nt][3]));
        }
        m0 = fmaxf(m0, __shfl_xor_sync(FULL, m0, 1));
        m0 = fmaxf(m0, __shfl_xor_sync(FULL, m0, 2));
        m1 = fmaxf(m1, __shfl_xor_sync(FULL, m1, 1));
        m1 = fmaxf(m1, __shfl_xor_sync(FULL, m1, 2));
        if (t == 0) {
            sExM[w * 16 + g]     = m0;
            sExM[w * 16 + 8 + g] = m1;
        }
        __syncthreads();   // S2

        const float pm0 = sExM[(w ^ 1) * 16 + g];
        const float pm1 = sExM[(w ^ 1) * 16 + 8 + g];
        const float mn0 = fmaxf(mr0, fmaxf(m0, pm0));
        const float mn1 = fmaxf(mr1, fmaxf(m1, pm1));
        const float corr0 = __expf(mr0 - mn0);
        const float corr1 = __expf(mr1 - mn1);
        mr0 = mn0; mr1 = mn1;

        // ---- exp, single half2 P write, row sums ----
        float s0 = 0.f, s1 = 0.f;
        #pragma unroll
        for (int nt = 0; nt < 4; nt++) {
            float p0 = __expf(pr[nt][0] - mn0);
            float p1 = __expf(pr[nt][1] - mn0);
            float p2 = __expf(pr[nt][2] - mn1);
            float p3 = __expf(pr[nt][3] - mn1);
            s0 += p0 + p1; s1 += p2 + p3;
            const int jq = half * 16 + nt * 4 + t;
            sP[(b * 16 + g) * QP + jq]     = f2h2(p0, p1);
            sP[(b * 16 + g + 8) * QP + jq] = f2h2(p2, p3);
        }
        s0 += __shfl_xor_sync(FULL, s0, 1);
        s0 += __shfl_xor_sync(FULL, s0, 2);
        s1 += __shfl_xor_sync(FULL, s1, 1);
        s1 += __shfl_xor_sync(FULL, s1, 2);
        if (t == 0) {
            sExS[w * 16 + g]     = s0;
            sExS[w * 16 + 8 + g] = s1;
        }

        asm volatile("cp.async.wait_group 0;" ::: "memory");
        __syncthreads();   // S3

        lr0 = lr0 * corr0 + s0 + sExS[(w ^ 1) * 16 + g];
        lr1 = lr1 * corr1 + s1 + sExS[(w ^ 1) * 16 + 8 + g];

        // ---- rescale ctx + AV MMA ----
        #pragma unroll
        for (int nt = 0; nt < 4; nt++) {
            cacc[nt][0] *= corr0; cacc[nt][1] *= corr0;
            cacc[nt][2] *= corr1; cacc[nt][3] *= corr1;
        }
        #pragma unroll
        for (int ks = 0; ks < 4; ks++) {
            const int kq = ks * 8;
            uint32_t af[4], bf[2];
            af[0] = sP[(b * 16 + g) * QP + kq + t];
            af[1] = sP[(b * 16 + g + 8) * QP + kq + t];
            af[2] = sP[(b * 16 + g) * QP + kq + t + 4];
            af[3] = sP[(b * 16 + g + 8) * QP + kq + t + 4];
            #pragma unroll
            for (int nt = 0; nt < 4; nt++) {
                const int n = half * 32 + nt * 8 + g;
                bf[0] = sV[(b * 64 + n) * QP + kq + t];
                bf[1] = sV[(b * 64 + n) * QP + kq + t + 4];
                mma_f16(cacc[nt], af, bf);
            }
        }
    }

    // ---- epilogue: normalize + write ctx as HALF [b][i][h*DH + d] ----
    {
        const float inv0 = 1.f / lr0;
        const float inv1 = 1.f / lr1;
        const size_t base = ((size_t)(b * SEQ) + i) * DM;
        #pragma unroll
        for (int nt = 0; nt < 4; nt++) {
            const int d = half * 32 + nt * 8 + 2 * t;
            *(uint32_t*)&ch[base + g * DH + d] =
                f2h2(cacc[nt][0] * inv0, cacc[nt][1] * inv0);
            *(uint32_t*)&ch[base + (g + 8) * DH + d] =
                f2h2(cacc[nt][2] * inv1, cacc[nt][3] * inv1);
        }
    }
}

// ---------------------------------------------------------------------------
extern "C" void kernel_launch(void* const* d_in, const int* in_sizes, int n_in,
                              void* d_out, int out_size)
{
    const float* x   = (const float*)d_in[0];
    const float* rel = (const float*)d_in[1];
    const float* Wq  = (const float*)d_in[2];
    const float* Wk  = (const float*)d_in[3];
    const float* Wv  = (const float*)d_in[4];
    const float* Wo  = (const float*)d_in[5];
    const float* bo  = (const float*)d_in[6];
    float* out = (float*)d_out;

    float *qb, *kb, *vb, *ctx;
    cudaGetSymbolAddress((void**)&qb,  g_q);
    cudaGetSymbolAddress((void**)&kb,  g_k);
    cudaGetSymbolAddress((void**)&vb,  g_v);
    cudaGetSymbolAddress((void**)&ctx, g_ctx);

    cudaFuncSetAttribute(attn_kernel,
                         cudaFuncAttributeMaxDynamicSharedMemorySize,
                         SM_ATTN_BYTES);

    const int M = BATCH * SEQ;  // 4096

    // fused q|k|v projections: x=0..7 -> q(half, permuted); x=8 -> k,v^T (half)
    {
        dim3 grid(9, M / 128);
        gemm_f16<4><<<grid, 256>>>(x, Wq, Wk, Wv, nullptr,
                                   qb, kb, vb, M, DM, DM);
    }
    // fused attention (fp16 MMA, cp.async V, half in/out)
    attn_kernel<<<SEQ, 256, SM_ATTN_BYTES>>>(rel, qb, kb, vb, ctx);

    // out = ctx(half) @ Wo^T + bo
    {
        dim3 grid(8, M / 128);
        gemm_f16<2><<<grid, 256>>>(ctx, Wo, nullptr, nullptr, bo,
                                   out, nullptr, nullptr, M, DM, DM);
    }
}